// round 12
// baseline (speedup 1.0000x reference)
#include <cuda_runtime.h>
#include <math.h>

// ---------------------------------------------------------------------------
// SlotAttention — B=32, F=4096, S=8, D=512, H=2048, 3 iterations.
// K/V never materialized. LN folded out of the feature pass algebraically.
// GEMMs: 128x64 tile, 8x4 micro, packed f32x2 FMA with DUPLICATED-B smem
// (no packing MOVs in the inner loop). Split-K + deterministic reduction.
// ---------------------------------------------------------------------------

#define B_ 32
#define F_ 4096
#define S_ 8
#define D_ 512
#define H_ 2048
#define NITERS_ 3
#define CHUNK 128
#define NCHUNK (F_ / CHUNK) /* 32 */

static __device__ __constant__ float kEPS = 1e-8f;
#define LN_EPS 1e-5f
#define SCALE_ 0.04419417382415922f /* 512^-0.5 */

typedef unsigned long long u64t;

// -------------------- packed f32x2 helpers ----------------------------------
__device__ __forceinline__ u64t f2pack(float x, float y) {
    u64t r;
    asm("mov.b64 %0, {%1, %2};" : "=l"(r) : "f"(x), "f"(y));
    return r;
}
__device__ __forceinline__ float2 f2unpack(u64t p) {
    float lo, hi;
    asm("mov.b64 {%0, %1}, %2;" : "=f"(lo), "=f"(hi) : "l"(p));
    return make_float2(lo, hi);
}
__device__ __forceinline__ void f2fma(u64t& d, u64t a, u64t b) {
    asm("fma.rn.f32x2 %0, %1, %2, %0;" : "+l"(d) : "l"(a), "l"(b));
}

// -------------------- scratch (device globals) ------------------------------
__device__ float g_stats[B_ * F_ * 2];
__device__ float g_Wqkhh[D_ * 2048];              // [Wqk | w_hh^T] (512 x 2048)
__device__ float g_bias2048[2048];                // [0 | b_hh]
__device__ float g_Wvih[D_ * 3 * D_];             // w_v @ w_ih^T (512 x 1536)
__device__ float g_sn[B_ * S_ * D_];
__device__ float g_qkgh[B_ * S_ * 2048];          // cols 0-511 qk, 512-2047 gh
__device__ float g_gi[B_ * S_ * 3 * D_];          // reused as Wqk tmp
__device__ float g_updates[B_ * S_ * D_];
__device__ float g_slots2[B_ * S_ * D_];
__device__ float g_mlpin[B_ * S_ * D_];
__device__ float g_hbuf[B_ * S_ * H_];
__device__ float g_split[8 * B_ * S_ * 2048];     // split-K partials (16 MB)
__device__ float g_Upart[B_ * NCHUNK * S_ * D_];  // 16 MB partials
__device__ float g_rspart[B_ * NCHUNK * S_];

// -------------------- small utility kernels --------------------------------
__global__ void feat_stats_kernel(const float* __restrict__ feat) {
    int row = blockIdx.x * 8 + (threadIdx.x >> 5);
    int lane = threadIdx.x & 31;
    const float4* r4 = (const float4*)(feat + (size_t)row * D_);
    float s = 0.f, ss = 0.f;
#pragma unroll
    for (int i = 0; i < 4; i++) {
        float4 v = r4[lane + 32 * i];
        s += v.x + v.y + v.z + v.w;
        ss += v.x * v.x + v.y * v.y + v.z * v.z + v.w * v.w;
    }
#pragma unroll
    for (int o = 16; o; o >>= 1) {
        s += __shfl_xor_sync(0xffffffffu, s, o);
        ss += __shfl_xor_sync(0xffffffffu, ss, o);
    }
    if (lane == 0) {
        float m = s * (1.f / D_);
        float var = ss * (1.f / D_) - m * m;
        g_stats[row * 2] = m;
        g_stats[row * 2 + 1] = rsqrtf(fmaxf(var, 0.f) + LN_EPS);
    }
}

// LayerNorm of [R, 512] rows -> Y (128 threads per row) — used only at iter 0
__global__ void ln_rows_kernel(const float* __restrict__ X, float* __restrict__ Y,
                               const float* __restrict__ w, const float* __restrict__ b) {
    __shared__ float red[48];
    int row = blockIdx.x;
    const float* x = X + (size_t)row * D_;
    int t = threadIdx.x;
    float v[4];
    float s = 0.f, ss = 0.f;
#pragma unroll
    for (int i = 0; i < 4; i++) {
        v[i] = x[t + 128 * i];
        s += v[i];
        ss += v[i] * v[i];
    }
#pragma unroll
    for (int o = 16; o; o >>= 1) {
        s += __shfl_xor_sync(0xffffffffu, s, o);
        ss += __shfl_xor_sync(0xffffffffu, ss, o);
    }
    int warp = t >> 5, lane = t & 31;
    if (lane == 0) { red[warp] = s; red[warp + 8] = ss; }
    __syncthreads();
    if (t == 0) {
        float S2 = 0.f, SS = 0.f;
        for (int wi = 0; wi < 4; wi++) { S2 += red[wi]; SS += red[wi + 8]; }
        float m = S2 * (1.f / D_);
        red[16] = m;
        red[17] = rsqrtf(fmaxf(SS * (1.f / D_) - m * m, 0.f) + LN_EPS);
    }
    __syncthreads();
    float m = red[16], r = red[17];
    float* y = Y + (size_t)row * D_;
#pragma unroll
    for (int i = 0; i < 4; i++) {
        int d = t + 128 * i;
        y[d] = (v[i] - m) * r * w[d] + b[d];
    }
}

// pack Wqkhh = [Wqk(from tmp) | w_hh^T]; bias2048 = [0 | b_hh]
__global__ void build_whh_kernel(const float* __restrict__ w_hh,
                                 const float* __restrict__ b_hh,
                                 const float* __restrict__ wqk_tmp) {
    int idx = blockIdx.x * 256 + threadIdx.x;   // < 512*2048
    int d = idx >> 11, col = idx & 2047;
    g_Wqkhh[idx] = (col < 512) ? wqk_tmp[(size_t)d * 512 + col]
                               : w_hh[(size_t)(col - 512) * 512 + d];
    if (idx < 2048) g_bias2048[idx] = (idx < 512) ? 0.f : b_hh[idx - 512];
}

// -------------------- SGEMM: 128x64x16 tiles, 256 threads, 8x4 micro --------
// Accumulators packed f32x2 along M. B staged DUPLICATED in smem so the inner
// loop needs no packing MOVs. Double-buffered smem. Split-K slabs.
template <bool TRANS_B>
__global__ void __launch_bounds__(256, 3)
gemm128_kernel(const float* __restrict__ A, const float* __restrict__ Bm,
               float* __restrict__ C, int M, int N, int K, int ldc) {
    __shared__ __align__(16) float As[2][16][128];
    __shared__ __align__(16) float Bs[2][16][128];   // duplicated (b,b) pairs
    const int tid = threadIdx.x;          // 256 threads
    const int bm = blockIdx.y * 128;
    const int bn = blockIdx.x * 64;
    const int Kz = K / gridDim.z;
    const int kbase = blockIdx.z * Kz;
    C += (size_t)blockIdx.z * M * ldc;

    const int tx = tid & 15, ty = tid >> 4;   // micro: 8 rows (4 pairs) x 4 cols
    const int a_m0 = tid >> 2;                // 0..63
    const int a_k  = (tid & 3) * 4;
    const int b_k = tid >> 4, b_n = (tid & 15) * 4;
    const int bt_n = tid >> 2;                // 0..63

    float4 pa0, pa1, pb;
    u64t acc[4][4];
#pragma unroll
    for (int i = 0; i < 4; i++)
#pragma unroll
        for (int j = 0; j < 4; j++) acc[i][j] = 0ull;

    const int nsteps = Kz / 16;

    pa0 = *(const float4*)(A + (size_t)(bm + a_m0) * K + kbase + a_k);
    pa1 = *(const float4*)(A + (size_t)(bm + a_m0 + 64) * K + kbase + a_k);
    if (TRANS_B)
        pb = *(const float4*)(Bm + (size_t)(bn + bt_n) * K + kbase + a_k);
    else
        pb = *(const float4*)(Bm + (size_t)(kbase + b_k) * N + bn + b_n);

    As[0][a_k + 0][a_m0] = pa0.x; As[0][a_k + 1][a_m0] = pa0.y;
    As[0][a_k + 2][a_m0] = pa0.z; As[0][a_k + 3][a_m0] = pa0.w;
    As[0][a_k + 0][a_m0 + 64] = pa1.x; As[0][a_k + 1][a_m0 + 64] = pa1.y;
    As[0][a_k + 2][a_m0 + 64] = pa1.z; As[0][a_k + 3][a_m0 + 64] = pa1.w;
    if (TRANS_B) {
        *(u64t*)&Bs[0][a_k + 0][bt_n * 2] = f2pack(pb.x, pb.x);
        *(u64t*)&Bs[0][a_k + 1][bt_n * 2] = f2pack(pb.y, pb.y);
        *(u64t*)&Bs[0][a_k + 2][bt_n * 2] = f2pack(pb.z, pb.z);
        *(u64t*)&Bs[0][a_k + 3][bt_n * 2] = f2pack(pb.w, pb.w);
    } else {
        *(float4*)&Bs[0][b_k][b_n * 2]     = make_float4(pb.x, pb.x, pb.y, pb.y);
        *(float4*)&Bs[0][b_k][b_n * 2 + 4] = make_float4(pb.z, pb.z, pb.w, pb.w);
    }
    __syncthreads();

    int buf = 0;
    for (int s = 0; s < nsteps; s++) {
        if (s + 1 < nsteps) {
            int kb = kbase + (s + 1) * 16;
            pa0 = *(const float4*)(A + (size_t)(bm + a_m0) * K + kb + a_k);
            pa1 = *(const float4*)(A + (size_t)(bm + a_m0 + 64) * K + kb + a_k);
            if (TRANS_B)
                pb = *(const float4*)(Bm + (size_t)(bn + bt_n) * K + kb + a_k);
            else
                pb = *(const float4*)(Bm + (size_t)(kb + b_k) * N + bn + b_n);
        }
#pragma unroll
        for (int k = 0; k < 16; k++) {
            const ulonglong2 ap01 = *(const ulonglong2*)&As[buf][k][ty * 8];
            const ulonglong2 ap23 = *(const ulonglong2*)&As[buf][k][ty * 8 + 4];
            const ulonglong2 bd01 = *(const ulonglong2*)&Bs[buf][k][tx * 8];
            const ulonglong2 bd23 = *(const ulonglong2*)&Bs[buf][k][tx * 8 + 4];
            u64t ap[4] = {ap01.x, ap01.y, ap23.x, ap23.y};
            u64t bd[4] = {bd01.x, bd01.y, bd23.x, bd23.y};
#pragma unroll
            for (int i = 0; i < 4; i++)
#pragma unroll
                for (int j = 0; j < 4; j++) f2fma(acc[i][j], ap[i], bd[j]);
        }
        if (s + 1 < nsteps) {
            int nb = buf ^ 1;
            As[nb][a_k + 0][a_m0] = pa0.x; As[nb][a_k + 1][a_m0] = pa0.y;
            As[nb][a_k + 2][a_m0] = pa0.z; As[nb][a_k + 3][a_m0] = pa0.w;
            As[nb][a_k + 0][a_m0 + 64] = pa1.x; As[nb][a_k + 1][a_m0 + 64] = pa1.y;
            As[nb][a_k + 2][a_m0 + 64] = pa1.z; As[nb][a_k + 3][a_m0 + 64] = pa1.w;
            if (TRANS_B) {
                *(u64t*)&Bs[nb][a_k + 0][bt_n * 2] = f2pack(pb.x, pb.x);
                *(u64t*)&Bs[nb][a_k + 1][bt_n * 2] = f2pack(pb.y, pb.y);
                *(u64t*)&Bs[nb][a_k + 2][bt_n * 2] = f2pack(pb.z, pb.z);
                *(u64t*)&Bs[nb][a_k + 3][bt_n * 2] = f2pack(pb.w, pb.w);
            } else {
                *(float4*)&Bs[nb][b_k][b_n * 2]     = make_float4(pb.x, pb.x, pb.y, pb.y);
                *(float4*)&Bs[nb][b_k][b_n * 2 + 4] = make_float4(pb.z, pb.z, pb.w, pb.w);
            }
            __syncthreads();
            buf = nb;
        }
    }
#pragma unroll
    for (int i2 = 0; i2 < 4; i2++) {
        float2 c0 = f2unpack(acc[i2][0]), c1 = f2unpack(acc[i2][1]);
        float2 c2 = f2unpack(acc[i2][2]), c3 = f2unpack(acc[i2][3]);
        int r0 = bm + ty * 8 + 2 * i2;
        *(float4*)(C + (size_t)r0 * ldc + bn + tx * 4) =
            make_float4(c0.x, c1.x, c2.x, c3.x);
        *(float4*)(C + (size_t)(r0 + 1) * ldc + bn + tx * 4) =
            make_float4(c0.y, c1.y, c2.y, c3.y);
    }
}

// deterministic split-K reduce (float4): out contiguous (ldo == ncols)
template <bool RELU>
__global__ void splitk_reduce(const float* __restrict__ bias, float* __restrict__ out,
                              int n, int ncols, int nsplit, int stride) {
    int i = (blockIdx.x * 256 + threadIdx.x) * 4;
    if (i >= n) return;
    float4 v = make_float4(0.f, 0.f, 0.f, 0.f);
    for (int z = 0; z < nsplit; z++) {
        const float4 p = *(const float4*)(g_split + (size_t)z * stride + i);
        v.x += p.x; v.y += p.y; v.z += p.z; v.w += p.w;
    }
    if (bias) {
        int col = i % ncols;
        const float4 bq = *(const float4*)(bias + col);
        v.x += bq.x; v.y += bq.y; v.z += bq.z; v.w += bq.w;
    }
    if (RELU) {
        v.x = fmaxf(v.x, 0.f); v.y = fmaxf(v.y, 0.f);
        v.z = fmaxf(v.z, 0.f); v.w = fmaxf(v.w, 0.f);
    }
    *(float4*)(out + i) = v;
}

// -------------------- fused row kernels (512 threads = 1 row) ---------------
__device__ __forceinline__ void block_ln_512(float v, float* red, int t,
                                             float& m_out, float& r_out) {
    float s = v, ss = v * v;
#pragma unroll
    for (int o = 16; o; o >>= 1) {
        s += __shfl_xor_sync(0xffffffffu, s, o);
        ss += __shfl_xor_sync(0xffffffffu, ss, o);
    }
    int warp = t >> 5, lane = t & 31;
    if (lane == 0) { red[warp] = s; red[warp + 16] = ss; }
    __syncthreads();
    if (t == 0) {
        float S2 = 0.f, SS = 0.f;
#pragma unroll
        for (int wi = 0; wi < 16; wi++) { S2 += red[wi]; SS += red[wi + 16]; }
        float m = S2 * (1.f / D_);
        red[32] = m;
        red[33] = rsqrtf(fmaxf(SS * (1.f / D_) - m * m, 0.f) + LN_EPS);
    }
    __syncthreads();
    m_out = red[32];
    r_out = red[33];
}

// gi split-8 reduce + GRU combine + LN(ln_mlp) -> slots2, mlpin.
__global__ void gru_ln_kernel(const float* __restrict__ b_ih,
                              const float* __restrict__ lnw, const float* __restrict__ lnb) {
    __shared__ float red[34];
    int r = blockIdx.x, d = threadIdx.x;
    float ir = b_ih[d], iz = b_ih[D_ + d], in_ = b_ih[2 * D_ + d];
    size_t base = (size_t)r * 3 * D_ + d;
#pragma unroll
    for (int zz = 0; zz < 8; zz++) {
        const float* sl = g_split + (size_t)zz * (B_ * S_ * 3 * D_);
        ir  += sl[base];
        iz  += sl[base + D_];
        in_ += sl[base + 2 * D_];
    }
    size_t ghb = (size_t)r * 2048 + 512;
    float hr = g_qkgh[ghb + d], hz = g_qkgh[ghb + D_ + d], hn = g_qkgh[ghb + 2 * D_ + d];
    float rg = 1.f / (1.f + expf(-(ir + hr)));
    float z  = 1.f / (1.f + expf(-(iz + hz)));
    float n  = tanhf(in_ + rg * hn);
    float v  = (1.f - z) * n + z * g_sn[(size_t)r * D_ + d];
    g_slots2[(size_t)r * D_ + d] = v;
    float m, rs;
    block_ln_512(v, red, d, m, rs);
    g_mlpin[(size_t)r * D_ + d] = (v - m) * rs * lnw[d] + lnb[d];
}

// mlp2 split-16 reduce + b2 + residual(slots2) + LN(ln_slot) -> sn (+out last)
__global__ void mlp2_reduce_ln(const float* __restrict__ b2,
                               const float* __restrict__ lnw, const float* __restrict__ lnb,
                               float* __restrict__ out_slots /* null unless last */) {
    __shared__ float red[34];
    int r = blockIdx.x, d = threadIdx.x;
    size_t i = (size_t)r * D_ + d;
    float v = b2[d] + g_slots2[i];
#pragma unroll
    for (int z = 0; z < 16; z++) v += g_split[(size_t)z * (B_ * S_ * D_) + i];
    if (out_slots) out_slots[i] = v;
    float m, rs;
    block_ln_512(v, red, d, m, rs);
    g_sn[i] = (v - m) * rs * lnw[d] + lnb[d];
}

// -------------------- fused per-iteration feature pass ----------------------
// LN folded out: dots = rstd*(x.wq - mean*swq) + cq ;  U = w*(sum(beta*x)-G)+b*A
__global__ void iter_pass_kernel(const float* __restrict__ feat,
                                 const float* __restrict__ lnw,
                                 const float* __restrict__ lnb,
                                 float* __restrict__ attn_out) {
    __shared__ __align__(16) float qk_s[S_ * D_];  // wq; reused as reduce buffer
    __shared__ __align__(16) float attn_s[CHUNK * S_];
    __shared__ __align__(16) u64t betasd_s[CHUNK * S_];   // duplicated (b,b)
    __shared__ __align__(16) float lnw_s[D_], lnb_s[D_];
    __shared__ float stats_s[CHUNK * 2];
    __shared__ float wsum_s[8][8], gsum_s[8][8];
    __shared__ float swq_s[8], cq_s[8], A_s[8], G_s[8];

    int chunk = blockIdx.x, b = blockIdx.y;
    int tid = threadIdx.x, warp = tid >> 5, lane = tid & 31;
    int f0 = chunk * CHUNK;

    for (int i = tid; i < D_; i += 256) { lnw_s[i] = lnw[i]; lnb_s[i] = lnb[i]; }
    for (int i = tid; i < CHUNK * 2; i += 256) stats_s[i] = g_stats[((size_t)b * F_ + f0) * 2 + i];
    __syncthreads();

    // ---- per-warp wq prep: warp w handles slot s=w ----
    {
        int s = warp;
        const float* qrow = g_qkgh + ((size_t)(b * 8 + s)) * 2048;
        float swq = 0.f, cq = 0.f;
#pragma unroll
        for (int i = 0; i < 4; i++) {
            int d4 = (lane + 32 * i) * 4;
            float4 q = *(const float4*)(qrow + d4);
            float4 w4 = *(const float4*)&lnw_s[d4];
            float4 b4 = *(const float4*)&lnb_s[d4];
            float4 wq = make_float4(q.x * w4.x, q.y * w4.y, q.z * w4.z, q.w * w4.w);
            *(float4*)&qk_s[s * D_ + d4] = wq;
            swq += wq.x + wq.y + wq.z + wq.w;
            cq  += b4.x * q.x + b4.y * q.y + b4.z * q.z + b4.w * q.w;
        }
#pragma unroll
        for (int o = 16; o; o >>= 1) {
            swq += __shfl_xor_sync(0xffffffffu, swq, o);
            cq  += __shfl_xor_sync(0xffffffffu, cq, o);
        }
        if (lane == 0) { swq_s[s] = swq; cq_s[s] = cq; }
    }
    __syncthreads();

    // slot owned by this lane after the fold-reduction: bits {4,3,2} of lane
    const int sIdx = (lane >> 2) & 7;
    const bool writer = (lane & 3) == 0;
    const float swq_r = swq_s[sIdx], cq_r = cq_s[sIdx];

    // ---- phase 1: one warp per feature row; raw dot + folded LN ----
    float wsum = 0.f, gsum = 0.f;   // meaningful on writer lanes
    for (int fl = warp; fl < CHUNK; fl += 8) {
        const ulonglong2* r2p = (const ulonglong2*)(feat + ((size_t)(b * F_ + f0 + fl)) * D_);
        u64t accp[8] = {};
#pragma unroll
        for (int i = 0; i < 4; i++) {
            int idx = lane + 32 * i;
            ulonglong2 xv = r2p[idx];
            int dbase = idx * 4;
#pragma unroll
            for (int s = 0; s < 8; s++) {
                const ulonglong2 qp = *(const ulonglong2*)&qk_s[s * D_ + dbase];
                f2fma(accp[s], xv.x, qp.x);
                f2fma(accp[s], xv.y, qp.y);
            }
        }
        float acc[8];
#pragma unroll
        for (int s = 0; s < 8; s++) {
            float2 u = f2unpack(accp[s]);
            acc[s] = u.x + u.y;
        }
        // fold-reduce: 8 slots x 32 lanes -> lane l holds full dot of slot (l>>2)&7
        float r4[4];
#pragma unroll
        for (int s = 0; s < 4; s++) {
            float mine  = (lane & 16) ? acc[s + 4] : acc[s];
            float other = (lane & 16) ? acc[s] : acc[s + 4];
            r4[s] = mine + __shfl_xor_sync(0xffffffffu, other, 16);
        }
        float r2v[2];
#pragma unroll
        for (int s = 0; s < 2; s++) {
            float mine  = (lane & 8) ? r4[s + 2] : r4[s];
            float other = (lane & 8) ? r4[s] : r4[s + 2];
            r2v[s] = mine + __shfl_xor_sync(0xffffffffu, other, 8);
        }
        {
            float mine  = (lane & 4) ? r2v[1] : r2v[0];
            float other = (lane & 4) ? r2v[0] : r2v[1];
            float r1 = mine + __shfl_xor_sync(0xffffffffu, other, 4);
            r1 += __shfl_xor_sync(0xffffffffu, r1, 2);
            r1 += __shfl_xor_sync(0xffffffffu, r1, 1);
            // r1 = full dot x.wq for slot sIdx
            float mean = stats_s[fl * 2], rstd = stats_s[fl * 2 + 1];
            float sc = (rstd * (r1 - mean * swq_r) + cq_r) * SCALE_;
            // softmax over slots: slots live on lanes differing in bits {2,3,4}
            float mx = sc;
            mx = fmaxf(mx, __shfl_xor_sync(0xffffffffu, mx, 4));
            mx = fmaxf(mx, __shfl_xor_sync(0xffffffffu, mx, 8));
            mx = fmaxf(mx, __shfl_xor_sync(0xffffffffu, mx, 16));
            float e = expf(sc - mx);
            float den = e;
            den += __shfl_xor_sync(0xffffffffu, den, 4);
            den += __shfl_xor_sync(0xffffffffu, den, 8);
            den += __shfl_xor_sync(0xffffffffu, den, 16);
            float p = e / den;
            if (writer) {
                attn_s[fl * 8 + sIdx] = p;
                float al = p + kEPS;
                float bt = al * rstd;
                betasd_s[fl * 8 + sIdx] = f2pack(bt, bt);
                wsum += al;
                gsum += bt * mean;
            }
        }
    }
    if (writer) { wsum_s[warp][sIdx] = wsum; gsum_s[warp][sIdx] = gsum; }
    __syncthreads();
    if (tid < 8) {
        float tA = 0.f, tG = 0.f;
#pragma unroll
        for (int w = 0; w < 8; w++) { tA += wsum_s[w][tid]; tG += gsum_s[w][tid]; }
        g_rspart[(b * NCHUNK + chunk) * 8 + tid] = tA;
        A_s[tid] = tA;
        G_s[tid] = tG;
    }
    if (attn_out) {
        for (int idx = tid; idx < CHUNK * S_; idx += 256) {
            int s = idx >> 7;
            int fl = idx & 127;
            attn_out[((size_t)(b * S_ + s)) * F_ + f0 + fl] = attn_s[fl * 8 + s];
        }
    }

    // ---- phase 2: sum(beta*x); x pairs free from LDG, betas dup from LDS ----
    int half = tid >> 7;              // 0: rows 0-63, 1: rows 64-127
    int d4 = (tid & 127) * 4;
    float4 w4 = *(const float4*)&lnw_s[d4];
    float4 b4 = *(const float4*)&lnb_s[d4];
    u64t accp2[2][8];                 // [col-pair][slot]
#pragma unroll
    for (int c = 0; c < 2; c++)
#pragma unroll
        for (int s = 0; s < 8; s++) accp2[c][s] = 0ull;

    int fl0 = half * 64;
    for (int fl = fl0; fl < fl0 + 64; fl++) {
        const ulonglong2 xv = *(const ulonglong2*)(feat + ((size_t)(b * F_ + f0 + fl)) * D_ + d4);
        const ulonglong2 bd01 = *(const ulonglong2*)&betasd_s[fl * 8];
        const ulonglong2 bd23 = *(const ulonglong2*)&betasd_s[fl * 8 + 2];
        const ulonglong2 bd45 = *(const ulonglong2*)&betasd_s[fl * 8 + 4];
        const ulonglong2 bd67 = *(const ulonglong2*)&betasd_s[fl * 8 + 6];
        u64t bd[8] = {bd01.x, bd01.y, bd23.x, bd23.y, bd45.x, bd45.y, bd67.x, bd67.y};
#pragma unroll
        for (int s = 0; s < 8; s++) {
            f2fma(accp2[0][s], xv.x, bd[s]);
            f2fma(accp2[1][s], xv.y, bd[s]);
        }
    }
    float4 acc8[8];
#pragma unroll
    for (int s = 0; s < 8; s++) {
        float2 u0 = f2unpack(accp2[0][s]);
        float2 u1 = f2unpack(accp2[1][s]);
        acc8[s] = make_float4(u0.x, u0.y, u1.x, u1.y);
    }
    __syncthreads();     // phase-1 reads of qk_s done; reuse as reduce buffer
    if (half == 0) {
#pragma unroll
        for (int s = 0; s < 8; s++) *(float4*)&qk_s[s * D_ + d4] = acc8[s];
    }
    __syncthreads();
    if (half == 1) {
        size_t base = ((size_t)(b * NCHUNK + chunk)) * S_ * D_;
#pragma unroll
        for (int s = 0; s < 8; s++) {
            float4 cmb = *(const float4*)&qk_s[s * D_ + d4];
            cmb.x += acc8[s].x; cmb.y += acc8[s].y;
            cmb.z += acc8[s].z; cmb.w += acc8[s].w;
            float A = A_s[s], G = G_s[s];
            float4 o;
            o.x = w4.x * (cmb.x - G) + b4.x * A;
            o.y = w4.y * (cmb.y - G) + b4.y * A;
            o.z = w4.z * (cmb.z - G) + b4.z * A;
            o.w = w4.w * (cmb.w - G) + b4.w * A;
            *(float4*)(&g_Upart[base + s * D_ + d4]) = o;
        }
    }
}

// deterministic reduction of partials + rowsum normalization
__global__ void reduce_updates_kernel() {
    int bs = blockIdx.x;           // b*8+s
    int b = bs >> 3, s = bs & 7;
    int d = threadIdx.x;           // 512 threads
    float rs = 0.f;
#pragma unroll
    for (int c = 0; c < NCHUNK; c++) rs += g_rspart[(b * NCHUNK + c) * 8 + s];
    float acc = 0.f;
    for (int c = 0; c < NCHUNK; c++)
        acc += g_Upart[(((size_t)(b * NCHUNK + c)) * S_ + s) * D_ + d];
    g_updates[(size_t)bs * D_ + d] = acc / rs;
}

// -------------------- host orchestration -----------------------------------
extern "C" void kernel_launch(void* const* d_in, const int* in_sizes, int n_in,
                              void* d_out, int out_size) {
    const float* slots_in = (const float*)d_in[0];
    const float* features = (const float*)d_in[1];
    const float* w_k      = (const float*)d_in[2];
    const float* w_v      = (const float*)d_in[3];
    const float* w_q      = (const float*)d_in[4];
    const float* ln_feat_w = (const float*)d_in[5];
    const float* ln_feat_b = (const float*)d_in[6];
    const float* ln_slot_w = (const float*)d_in[7];
    const float* ln_slot_b = (const float*)d_in[8];
    const float* gru_w_ih = (const float*)d_in[9];
    const float* gru_w_hh = (const float*)d_in[10];
    const float* gru_b_ih = (const float*)d_in[11];
    const float* gru_b_hh = (const float*)d_in[12];
    const float* ln_mlp_w = (const float*)d_in[13];
    const float* ln_mlp_b = (const float*)d_in[14];
    const float* mlp_w1   = (const float*)d_in[15];
    const float* mlp_b1   = (const float*)d_in[16];
    const float* mlp_w2   = (const float*)d_in[17];
    const float* mlp_b2   = (const float*)d_in[18];

    float* out = (float*)d_out;
    float* out_slots = out;                      // [32,8,512]
    float* out_attn  = out + B_ * S_ * D_;       // [32,8,4096]

    float *p_Wqkhh, *p_bias2048, *p_Wvih, *p_sn, *p_qkgh, *p_gi,
          *p_updates, *p_mlpin, *p_hbuf, *p_split;
    cudaGetSymbolAddress((void**)&p_Wqkhh, g_Wqkhh);
    cudaGetSymbolAddress((void**)&p_bias2048, g_bias2048);
    cudaGetSymbolAddress((void**)&p_Wvih, g_Wvih);
    cudaGetSymbolAddress((void**)&p_sn, g_sn);
    cudaGetSymbolAddress((void**)&p_qkgh, g_qkgh);
    cudaGetSymbolAddress((void**)&p_gi, g_gi);
    cudaGetSymbolAddress((void**)&p_updates, g_updates);
    cudaGetSymbolAddress((void**)&p_mlpin, g_mlpin);
    cudaGetSymbolAddress((void**)&p_hbuf, g_hbuf);
    cudaGetSymbolAddress((void**)&p_split, g_split);

    const int NS = B_ * S_;          // 256 slot rows

    // -------- precomputes --------
    feat_stats_kernel<<<(B_ * F_) / 8, 256>>>(features);
    // Wqk tmp = w_q @ w_k^T  (NT, split-8 Kz=64) -> g_gi tmp
    gemm128_kernel<true><<<dim3(8, 4, 8), 256>>>(w_q, w_k, p_split, D_, D_, D_, D_);
    splitk_reduce<false><<<(512 * 512 / 4 + 255) / 256, 256>>>(nullptr, p_gi,
        512 * 512, 512, 8, 512 * 512);
    // W_vih = w_v @ w_ih^T  (NT, split-4 Kz=128)
    gemm128_kernel<true><<<dim3(24, 4, 4), 256>>>(w_v, gru_w_ih, p_split, D_, 3 * D_, D_, 3 * D_);
    splitk_reduce<false><<<(512 * 1536 / 4 + 255) / 256, 256>>>(nullptr, p_Wvih,
        512 * 1536, 1536, 4, 512 * 1536);
    // pack Wqkhh + bias
    build_whh_kernel<<<(512 * 2048) / 256, 256>>>(gru_w_hh, gru_b_hh, p_gi);

    for (int it = 0; it < NITERS_; it++) {
        bool last = (it == NITERS_ - 1);

        if (it == 0)
            ln_rows_kernel<<<NS, 128>>>(slots_in, p_sn, ln_slot_w, ln_slot_b);

        // [qk | gh] = s_n @ Wqkhh + [0 | b_hh]   (NN, N=2048, split-8 Kz=64)
        gemm128_kernel<false><<<dim3(32, 2, 8), 256>>>(p_sn, p_Wqkhh, p_split,
                                                       NS, 2048, D_, 2048);
        splitk_reduce<false><<<(NS * 2048 / 4 + 255) / 256, 256>>>(p_bias2048, p_qkgh,
            NS * 2048, 2048, 8, NS * 2048);

        // fused attention pass over features
        iter_pass_kernel<<<dim3(NCHUNK, B_), 256>>>(features, ln_feat_w, ln_feat_b,
                                                    last ? out_attn : nullptr);
        reduce_updates_kernel<<<NS, D_>>>();

        // gi partials = updates @ W_vih   (NN, N=1536, split-8 Kz=64)
        gemm128_kernel<false><<<dim3(24, 2, 8), 256>>>(p_updates, p_Wvih, p_split,
                                                       NS, 3 * D_, D_, 3 * D_);
        // fused: gi reduce + b_ih + GRU combine + LN(mlp)
        gru_ln_kernel<<<NS, D_>>>(gru_b_ih, ln_mlp_w, ln_mlp_b);

        // mlp1 = relu(mlpin @ w1 + b1)   (NN, N=2048, split-8 Kz=64)
        gemm128_kernel<false><<<dim3(32, 2, 8), 256>>>(p_mlpin, mlp_w1, p_split,
                                                       NS, H_, D_, H_);
        splitk_reduce<true><<<(NS * 2048 / 4 + 255) / 256, 256>>>(mlp_b1, p_hbuf,
            NS * 2048, 2048, 8, NS * 2048);

        // mlp2 partials (NN, N=512, K=2048, split-16 Kz=128)
        gemm128_kernel<false><<<dim3(8, 2, 16), 256>>>(p_hbuf, mlp_w2, p_split,
                                                       NS, D_, H_, D_);
        // reduce + bias + residual + LN(slot) -> sn (and out_slots if last)
        mlp2_reduce_ln<<<NS, D_>>>(mlp_b2, ln_slot_w, ln_slot_b,
                                   last ? out_slots : nullptr);
    }
}

// round 13
// speedup vs baseline: 1.1575x; 1.1575x over previous
#include <cuda_runtime.h>
#include <math.h>

// ---------------------------------------------------------------------------
// SlotAttention — B=32, F=4096, S=8, D=512, H=2048, 3 iterations.
// K/V never materialized. LN folded out of the feature pass algebraically.
// GEMMs: 128x64 tile, 8x4 micro, packed f32x2 FMA (compact B smem; R11-proven
// layout). Split-K + deterministic fixed-order reduction.
// ---------------------------------------------------------------------------

#define B_ 32
#define F_ 4096
#define S_ 8
#define D_ 512
#define H_ 2048
#define NITERS_ 3
#define CHUNK 128
#define NCHUNK (F_ / CHUNK) /* 32 */

static __device__ __constant__ float kEPS = 1e-8f;
#define LN_EPS 1e-5f
#define SCALE_ 0.04419417382415922f /* 512^-0.5 */

typedef unsigned long long u64t;

// -------------------- packed f32x2 helpers ----------------------------------
__device__ __forceinline__ u64t f2pack(float x, float y) {
    u64t r;
    asm("mov.b64 %0, {%1, %2};" : "=l"(r) : "f"(x), "f"(y));
    return r;
}
__device__ __forceinline__ float2 f2unpack(u64t p) {
    float lo, hi;
    asm("mov.b64 {%0, %1}, %2;" : "=f"(lo), "=f"(hi) : "l"(p));
    return make_float2(lo, hi);
}
__device__ __forceinline__ void f2fma(u64t& d, u64t a, u64t b) {
    asm("fma.rn.f32x2 %0, %1, %2, %0;" : "+l"(d) : "l"(a), "l"(b));
}

// -------------------- scratch (device globals) ------------------------------
__device__ float g_stats[B_ * F_ * 2];
__device__ float g_Wqkhh[D_ * 2048];              // [Wqk | w_hh^T] (512 x 2048)
__device__ float g_bias2048[2048];                // [0 | b_hh]
__device__ float g_Wvih[D_ * 3 * D_];             // w_v @ w_ih^T (512 x 1536)
__device__ float g_sn[B_ * S_ * D_];
__device__ float g_qkgh[B_ * S_ * 2048];          // cols 0-511 qk, 512-2047 gh
__device__ float g_gi[B_ * S_ * 3 * D_];          // reused as Wqk tmp
__device__ float g_updates[B_ * S_ * D_];
__device__ float g_slots2[B_ * S_ * D_];
__device__ float g_mlpin[B_ * S_ * D_];
__device__ float g_hbuf[B_ * S_ * H_];
__device__ float g_split[8 * B_ * S_ * 2048];     // split-K partials (16 MB)
__device__ float g_Upart[B_ * NCHUNK * S_ * D_];  // 16 MB partials
__device__ float g_rspart[B_ * NCHUNK * S_];

// -------------------- small utility kernels --------------------------------
__global__ void feat_stats_kernel(const float* __restrict__ feat) {
    int row = blockIdx.x * 8 + (threadIdx.x >> 5);
    int lane = threadIdx.x & 31;
    const float4* r4 = (const float4*)(feat + (size_t)row * D_);
    float s = 0.f, ss = 0.f;
#pragma unroll
    for (int i = 0; i < 4; i++) {
        float4 v = r4[lane + 32 * i];
        s += v.x + v.y + v.z + v.w;
        ss += v.x * v.x + v.y * v.y + v.z * v.z + v.w * v.w;
    }
#pragma unroll
    for (int o = 16; o; o >>= 1) {
        s += __shfl_xor_sync(0xffffffffu, s, o);
        ss += __shfl_xor_sync(0xffffffffu, ss, o);
    }
    if (lane == 0) {
        float m = s * (1.f / D_);
        float var = ss * (1.f / D_) - m * m;
        g_stats[row * 2] = m;
        g_stats[row * 2 + 1] = rsqrtf(fmaxf(var, 0.f) + LN_EPS);
    }
}

// LayerNorm of [R, 512] rows -> Y (128 threads per row) — used only at iter 0
__global__ void ln_rows_kernel(const float* __restrict__ X, float* __restrict__ Y,
                               const float* __restrict__ w, const float* __restrict__ b) {
    __shared__ float red[48];
    int row = blockIdx.x;
    const float* x = X + (size_t)row * D_;
    int t = threadIdx.x;
    float v[4];
    float s = 0.f, ss = 0.f;
#pragma unroll
    for (int i = 0; i < 4; i++) {
        v[i] = x[t + 128 * i];
        s += v[i];
        ss += v[i] * v[i];
    }
#pragma unroll
    for (int o = 16; o; o >>= 1) {
        s += __shfl_xor_sync(0xffffffffu, s, o);
        ss += __shfl_xor_sync(0xffffffffu, ss, o);
    }
    int warp = t >> 5, lane = t & 31;
    if (lane == 0) { red[warp] = s; red[warp + 8] = ss; }
    __syncthreads();
    if (t == 0) {
        float S2 = 0.f, SS = 0.f;
        for (int wi = 0; wi < 4; wi++) { S2 += red[wi]; SS += red[wi + 8]; }
        float m = S2 * (1.f / D_);
        red[16] = m;
        red[17] = rsqrtf(fmaxf(SS * (1.f / D_) - m * m, 0.f) + LN_EPS);
    }
    __syncthreads();
    float m = red[16], r = red[17];
    float* y = Y + (size_t)row * D_;
#pragma unroll
    for (int i = 0; i < 4; i++) {
        int d = t + 128 * i;
        y[d] = (v[i] - m) * r * w[d] + b[d];
    }
}

// pack Wqkhh = [Wqk(from tmp) | w_hh^T]; bias2048 = [0 | b_hh]
__global__ void build_whh_kernel(const float* __restrict__ w_hh,
                                 const float* __restrict__ b_hh,
                                 const float* __restrict__ wqk_tmp) {
    int idx = blockIdx.x * 256 + threadIdx.x;   // < 512*2048
    int d = idx >> 11, col = idx & 2047;
    g_Wqkhh[idx] = (col < 512) ? wqk_tmp[(size_t)d * 512 + col]
                               : w_hh[(size_t)(col - 512) * 512 + d];
    if (idx < 2048) g_bias2048[idx] = (idx < 512) ? 0.f : b_hh[idx - 512];
}

// -------------------- SGEMM: 128x64x16 tiles, 256 threads, 8x4 micro --------
// Accumulators packed f32x2 along M (A-pairs free from LDS.128 of k-major As).
// Compact B smem (R11-proven). Double-buffered. Split-K slabs.
template <bool TRANS_B>
__global__ void __launch_bounds__(256, 3)
gemm128_kernel(const float* __restrict__ A, const float* __restrict__ Bm,
               float* __restrict__ C, int M, int N, int K, int ldc) {
    __shared__ __align__(16) float As[2][16][128];
    __shared__ __align__(16) float Bs[2][16][64];
    const int tid = threadIdx.x;          // 256 threads
    const int bm = blockIdx.y * 128;
    const int bn = blockIdx.x * 64;
    const int Kz = K / gridDim.z;
    const int kbase = blockIdx.z * Kz;
    C += (size_t)blockIdx.z * M * ldc;

    const int tx = tid & 15, ty = tid >> 4;   // micro: 8 rows (4 pairs) x 4 cols
    const int a_m0 = tid >> 2;                // 0..63
    const int a_k  = (tid & 3) * 4;
    const int b_k = tid >> 4, b_n = (tid & 15) * 4;
    const int bt_n = tid >> 2;                // 0..63

    float4 pa0, pa1, pb;
    u64t acc[4][4];
#pragma unroll
    for (int i = 0; i < 4; i++)
#pragma unroll
        for (int j = 0; j < 4; j++) acc[i][j] = 0ull;

    const int nsteps = Kz / 16;

    pa0 = *(const float4*)(A + (size_t)(bm + a_m0) * K + kbase + a_k);
    pa1 = *(const float4*)(A + (size_t)(bm + a_m0 + 64) * K + kbase + a_k);
    if (TRANS_B)
        pb = *(const float4*)(Bm + (size_t)(bn + bt_n) * K + kbase + a_k);
    else
        pb = *(const float4*)(Bm + (size_t)(kbase + b_k) * N + bn + b_n);

    As[0][a_k + 0][a_m0] = pa0.x; As[0][a_k + 1][a_m0] = pa0.y;
    As[0][a_k + 2][a_m0] = pa0.z; As[0][a_k + 3][a_m0] = pa0.w;
    As[0][a_k + 0][a_m0 + 64] = pa1.x; As[0][a_k + 1][a_m0 + 64] = pa1.y;
    As[0][a_k + 2][a_m0 + 64] = pa1.z; As[0][a_k + 3][a_m0 + 64] = pa1.w;
    if (TRANS_B) {
        Bs[0][a_k + 0][bt_n] = pb.x; Bs[0][a_k + 1][bt_n] = pb.y;
        Bs[0][a_k + 2][bt_n] = pb.z; Bs[0][a_k + 3][bt_n] = pb.w;
    } else {
        *(float4*)&Bs[0][b_k][b_n] = pb;
    }
    __syncthreads();

    int buf = 0;
    for (int s = 0; s < nsteps; s++) {
        if (s + 1 < nsteps) {
            int kb = kbase + (s + 1) * 16;
            pa0 = *(const float4*)(A + (size_t)(bm + a_m0) * K + kb + a_k);
            pa1 = *(const float4*)(A + (size_t)(bm + a_m0 + 64) * K + kb + a_k);
            if (TRANS_B)
                pb = *(const float4*)(Bm + (size_t)(bn + bt_n) * K + kb + a_k);
            else
                pb = *(const float4*)(Bm + (size_t)(kb + b_k) * N + bn + b_n);
        }
#pragma unroll
        for (int k = 0; k < 16; k++) {
            const ulonglong2 ap01 = *(const ulonglong2*)&As[buf][k][ty * 8];
            const ulonglong2 ap23 = *(const ulonglong2*)&As[buf][k][ty * 8 + 4];
            const float4 b4 = *(const float4*)&Bs[buf][k][tx * 4];
            u64t ap[4] = {ap01.x, ap01.y, ap23.x, ap23.y};
            u64t bd[4];
            bd[0] = f2pack(b4.x, b4.x); bd[1] = f2pack(b4.y, b4.y);
            bd[2] = f2pack(b4.z, b4.z); bd[3] = f2pack(b4.w, b4.w);
#pragma unroll
            for (int i = 0; i < 4; i++)
#pragma unroll
                for (int j = 0; j < 4; j++) f2fma(acc[i][j], ap[i], bd[j]);
        }
        if (s + 1 < nsteps) {
            int nb = buf ^ 1;
            As[nb][a_k + 0][a_m0] = pa0.x; As[nb][a_k + 1][a_m0] = pa0.y;
            As[nb][a_k + 2][a_m0] = pa0.z; As[nb][a_k + 3][a_m0] = pa0.w;
            As[nb][a_k + 0][a_m0 + 64] = pa1.x; As[nb][a_k + 1][a_m0 + 64] = pa1.y;
            As[nb][a_k + 2][a_m0 + 64] = pa1.z; As[nb][a_k + 3][a_m0 + 64] = pa1.w;
            if (TRANS_B) {
                Bs[nb][a_k + 0][bt_n] = pb.x; Bs[nb][a_k + 1][bt_n] = pb.y;
                Bs[nb][a_k + 2][bt_n] = pb.z; Bs[nb][a_k + 3][bt_n] = pb.w;
            } else {
                *(float4*)&Bs[nb][b_k][b_n] = pb;
            }
            __syncthreads();
            buf = nb;
        }
    }
#pragma unroll
    for (int i2 = 0; i2 < 4; i2++) {
        float2 c0 = f2unpack(acc[i2][0]), c1 = f2unpack(acc[i2][1]);
        float2 c2 = f2unpack(acc[i2][2]), c3 = f2unpack(acc[i2][3]);
        int r0 = bm + ty * 8 + 2 * i2;
        *(float4*)(C + (size_t)r0 * ldc + bn + tx * 4) =
            make_float4(c0.x, c1.x, c2.x, c3.x);
        *(float4*)(C + (size_t)(r0 + 1) * ldc + bn + tx * 4) =
            make_float4(c0.y, c1.y, c2.y, c3.y);
    }
}

// deterministic split-K reduce (float4): out contiguous (ldo == ncols)
template <bool RELU>
__global__ void splitk_reduce(const float* __restrict__ bias, float* __restrict__ out,
                              int n, int ncols, int nsplit, int stride) {
    int i = (blockIdx.x * 256 + threadIdx.x) * 4;
    if (i >= n) return;
    float4 v = make_float4(0.f, 0.f, 0.f, 0.f);
    for (int z = 0; z < nsplit; z++) {
        const float4 p = *(const float4*)(g_split + (size_t)z * stride + i);
        v.x += p.x; v.y += p.y; v.z += p.z; v.w += p.w;
    }
    if (bias) {
        int col = i % ncols;
        const float4 bq = *(const float4*)(bias + col);
        v.x += bq.x; v.y += bq.y; v.z += bq.z; v.w += bq.w;
    }
    if (RELU) {
        v.x = fmaxf(v.x, 0.f); v.y = fmaxf(v.y, 0.f);
        v.z = fmaxf(v.z, 0.f); v.w = fmaxf(v.w, 0.f);
    }
    *(float4*)(out + i) = v;
}

// -------------------- fused row kernels (512 threads = 1 row) ---------------
__device__ __forceinline__ void block_ln_512(float v, float* red, int t,
                                             float& m_out, float& r_out) {
    float s = v, ss = v * v;
#pragma unroll
    for (int o = 16; o; o >>= 1) {
        s += __shfl_xor_sync(0xffffffffu, s, o);
        ss += __shfl_xor_sync(0xffffffffu, ss, o);
    }
    int warp = t >> 5, lane = t & 31;
    if (lane == 0) { red[warp] = s; red[warp + 16] = ss; }
    __syncthreads();
    if (t == 0) {
        float S2 = 0.f, SS = 0.f;
#pragma unroll
        for (int wi = 0; wi < 16; wi++) { S2 += red[wi]; SS += red[wi + 16]; }
        float m = S2 * (1.f / D_);
        red[32] = m;
        red[33] = rsqrtf(fmaxf(SS * (1.f / D_) - m * m, 0.f) + LN_EPS);
    }
    __syncthreads();
    m_out = red[32];
    r_out = red[33];
}

// gi split-8 reduce + GRU combine + LN(ln_mlp) -> slots2, mlpin.
__global__ void gru_ln_kernel(const float* __restrict__ b_ih,
                              const float* __restrict__ lnw, const float* __restrict__ lnb) {
    __shared__ float red[34];
    int r = blockIdx.x, d = threadIdx.x;
    float ir = b_ih[d], iz = b_ih[D_ + d], in_ = b_ih[2 * D_ + d];
    size_t base = (size_t)r * 3 * D_ + d;
#pragma unroll
    for (int zz = 0; zz < 8; zz++) {
        const float* sl = g_split + (size_t)zz * (B_ * S_ * 3 * D_);
        ir  += sl[base];
        iz  += sl[base + D_];
        in_ += sl[base + 2 * D_];
    }
    size_t ghb = (size_t)r * 2048 + 512;
    float hr = g_qkgh[ghb + d], hz = g_qkgh[ghb + D_ + d], hn = g_qkgh[ghb + 2 * D_ + d];
    float rg = 1.f / (1.f + expf(-(ir + hr)));
    float z  = 1.f / (1.f + expf(-(iz + hz)));
    float n  = tanhf(in_ + rg * hn);
    float v  = (1.f - z) * n + z * g_sn[(size_t)r * D_ + d];
    g_slots2[(size_t)r * D_ + d] = v;
    float m, rs;
    block_ln_512(v, red, d, m, rs);
    g_mlpin[(size_t)r * D_ + d] = (v - m) * rs * lnw[d] + lnb[d];
}

// mlp2 split-16 reduce + b2 + residual(slots2) + LN(ln_slot) -> sn (+out last)
__global__ void mlp2_reduce_ln(const float* __restrict__ b2,
                               const float* __restrict__ lnw, const float* __restrict__ lnb,
                               float* __restrict__ out_slots /* null unless last */) {
    __shared__ float red[34];
    int r = blockIdx.x, d = threadIdx.x;
    size_t i = (size_t)r * D_ + d;
    float v = b2[d] + g_slots2[i];
#pragma unroll
    for (int z = 0; z < 16; z++) v += g_split[(size_t)z * (B_ * S_ * D_) + i];
    if (out_slots) out_slots[i] = v;
    float m, rs;
    block_ln_512(v, red, d, m, rs);
    g_sn[i] = (v - m) * rs * lnw[d] + lnb[d];
}

// -------------------- fused per-iteration feature pass ----------------------
// LN folded out: dots = rstd*(x.wq - mean*swq) + cq ;  U = w*(sum(beta*x)-G)+b*A
__global__ void iter_pass_kernel(const float* __restrict__ feat,
                                 const float* __restrict__ lnw,
                                 const float* __restrict__ lnb,
                                 float* __restrict__ attn_out) {
    __shared__ __align__(16) float qk_s[S_ * D_];  // wq; reused as reduce buffer
    __shared__ __align__(16) float attn_s[CHUNK * S_];
    __shared__ __align__(16) u64t betasd_s[CHUNK * S_];   // duplicated (b,b)
    __shared__ __align__(16) float lnw_s[D_], lnb_s[D_];
    __shared__ float stats_s[CHUNK * 2];
    __shared__ float wsum_s[8][8], gsum_s[8][8];
    __shared__ float swq_s[8], cq_s[8], A_s[8], G_s[8];

    int chunk = blockIdx.x, b = blockIdx.y;
    int tid = threadIdx.x, warp = tid >> 5, lane = tid & 31;
    int f0 = chunk * CHUNK;

    for (int i = tid; i < D_; i += 256) { lnw_s[i] = lnw[i]; lnb_s[i] = lnb[i]; }
    for (int i = tid; i < CHUNK * 2; i += 256) stats_s[i] = g_stats[((size_t)b * F_ + f0) * 2 + i];
    __syncthreads();

    // ---- per-warp wq prep: warp w handles slot s=w ----
    {
        int s = warp;
        const float* qrow = g_qkgh + ((size_t)(b * 8 + s)) * 2048;
        float swq = 0.f, cq = 0.f;
#pragma unroll
        for (int i = 0; i < 4; i++) {
            int d4 = (lane + 32 * i) * 4;
            float4 q = *(const float4*)(qrow + d4);
            float4 w4 = *(const float4*)&lnw_s[d4];
            float4 b4 = *(const float4*)&lnb_s[d4];
            float4 wq = make_float4(q.x * w4.x, q.y * w4.y, q.z * w4.z, q.w * w4.w);
            *(float4*)&qk_s[s * D_ + d4] = wq;
            swq += wq.x + wq.y + wq.z + wq.w;
            cq  += b4.x * q.x + b4.y * q.y + b4.z * q.z + b4.w * q.w;
        }
#pragma unroll
        for (int o = 16; o; o >>= 1) {
            swq += __shfl_xor_sync(0xffffffffu, swq, o);
            cq  += __shfl_xor_sync(0xffffffffu, cq, o);
        }
        if (lane == 0) { swq_s[s] = swq; cq_s[s] = cq; }
    }
    __syncthreads();

    // slot owned by this lane after the fold-reduction: bits {4,3,2} of lane
    const int sIdx = (lane >> 2) & 7;
    const bool writer = (lane & 3) == 0;
    const float swq_r = swq_s[sIdx], cq_r = cq_s[sIdx];

    // ---- phase 1: one warp per feature row; raw dot + folded LN ----
    float wsum = 0.f, gsum = 0.f;   // meaningful on writer lanes
    for (int fl = warp; fl < CHUNK; fl += 8) {
        const ulonglong2* r2p = (const ulonglong2*)(feat + ((size_t)(b * F_ + f0 + fl)) * D_);
        u64t accp[8] = {};
#pragma unroll
        for (int i = 0; i < 4; i++) {
            int idx = lane + 32 * i;
            ulonglong2 xv = r2p[idx];
            int dbase = idx * 4;
#pragma unroll
            for (int s = 0; s < 8; s++) {
                const ulonglong2 qp = *(const ulonglong2*)&qk_s[s * D_ + dbase];
                f2fma(accp[s], xv.x, qp.x);
                f2fma(accp[s], xv.y, qp.y);
            }
        }
        float acc[8];
#pragma unroll
        for (int s = 0; s < 8; s++) {
            float2 u = f2unpack(accp[s]);
            acc[s] = u.x + u.y;
        }
        // fold-reduce: 8 slots x 32 lanes -> lane l holds full dot of slot (l>>2)&7
        float r4[4];
#pragma unroll
        for (int s = 0; s < 4; s++) {
            float mine  = (lane & 16) ? acc[s + 4] : acc[s];
            float other = (lane & 16) ? acc[s] : acc[s + 4];
            r4[s] = mine + __shfl_xor_sync(0xffffffffu, other, 16);
        }
        float r2v[2];
#pragma unroll
        for (int s = 0; s < 2; s++) {
            float mine  = (lane & 8) ? r4[s + 2] : r4[s];
            float other = (lane & 8) ? r4[s] : r4[s + 2];
            r2v[s] = mine + __shfl_xor_sync(0xffffffffu, other, 8);
        }
        {
            float mine  = (lane & 4) ? r2v[1] : r2v[0];
            float other = (lane & 4) ? r2v[0] : r2v[1];
            float r1 = mine + __shfl_xor_sync(0xffffffffu, other, 4);
            r1 += __shfl_xor_sync(0xffffffffu, r1, 2);
            r1 += __shfl_xor_sync(0xffffffffu, r1, 1);
            // r1 = full dot x.wq for slot sIdx
            float mean = stats_s[fl * 2], rstd = stats_s[fl * 2 + 1];
            float sc = (rstd * (r1 - mean * swq_r) + cq_r) * SCALE_;
            // softmax over slots: slots live on lanes differing in bits {2,3,4}
            float mx = sc;
            mx = fmaxf(mx, __shfl_xor_sync(0xffffffffu, mx, 4));
            mx = fmaxf(mx, __shfl_xor_sync(0xffffffffu, mx, 8));
            mx = fmaxf(mx, __shfl_xor_sync(0xffffffffu, mx, 16));
            float e = expf(sc - mx);
            float den = e;
            den += __shfl_xor_sync(0xffffffffu, den, 4);
            den += __shfl_xor_sync(0xffffffffu, den, 8);
            den += __shfl_xor_sync(0xffffffffu, den, 16);
            float p = e / den;
            if (writer) {
                attn_s[fl * 8 + sIdx] = p;
                float al = p + kEPS;
                float bt = al * rstd;
                betasd_s[fl * 8 + sIdx] = f2pack(bt, bt);
                wsum += al;
                gsum += bt * mean;
            }
        }
    }
    if (writer) { wsum_s[warp][sIdx] = wsum; gsum_s[warp][sIdx] = gsum; }
    __syncthreads();
    if (tid < 8) {
        float tA = 0.f, tG = 0.f;
#pragma unroll
        for (int w = 0; w < 8; w++) { tA += wsum_s[w][tid]; tG += gsum_s[w][tid]; }
        g_rspart[(b * NCHUNK + chunk) * 8 + tid] = tA;
        A_s[tid] = tA;
        G_s[tid] = tG;
    }
    if (attn_out) {
        for (int idx = tid; idx < CHUNK * S_; idx += 256) {
            int s = idx >> 7;
            int fl = idx & 127;
            attn_out[((size_t)(b * S_ + s)) * F_ + f0 + fl] = attn_s[fl * 8 + s];
        }
    }

    // ---- phase 2: sum(beta*x); x pairs free from LDG, betas dup from LDS ----
    int half = tid >> 7;              // 0: rows 0-63, 1: rows 64-127
    int d4 = (tid & 127) * 4;
    float4 w4 = *(const float4*)&lnw_s[d4];
    float4 b4 = *(const float4*)&lnb_s[d4];
    u64t accp2[2][8];                 // [col-pair][slot]
#pragma unroll
    for (int c = 0; c < 2; c++)
#pragma unroll
        for (int s = 0; s < 8; s++) accp2[c][s] = 0ull;

    int fl0 = half * 64;
    for (int fl = fl0; fl < fl0 + 64; fl++) {
        const ulonglong2 xv = *(const ulonglong2*)(feat + ((size_t)(b * F_ + f0 + fl)) * D_ + d4);
        const ulonglong2 bd01 = *(const ulonglong2*)&betasd_s[fl * 8];
        const ulonglong2 bd23 = *(const ulonglong2*)&betasd_s[fl * 8 + 2];
        const ulonglong2 bd45 = *(const ulonglong2*)&betasd_s[fl * 8 + 4];
        const ulonglong2 bd67 = *(const ulonglong2*)&betasd_s[fl * 8 + 6];
        u64t bd[8] = {bd01.x, bd01.y, bd23.x, bd23.y, bd45.x, bd45.y, bd67.x, bd67.y};
#pragma unroll
        for (int s = 0; s < 8; s++) {
            f2fma(accp2[0][s], xv.x, bd[s]);
            f2fma(accp2[1][s], xv.y, bd[s]);
        }
    }
    float4 acc8[8];
#pragma unroll
    for (int s = 0; s < 8; s++) {
        float2 u0 = f2unpack(accp2[0][s]);
        float2 u1 = f2unpack(accp2[1][s]);
        acc8[s] = make_float4(u0.x, u0.y, u1.x, u1.y);
    }
    __syncthreads();     // phase-1 reads of qk_s done; reuse as reduce buffer
    if (half == 0) {
#pragma unroll
        for (int s = 0; s < 8; s++) *(float4*)&qk_s[s * D_ + d4] = acc8[s];
    }
    __syncthreads();
    if (half == 1) {
        size_t base = ((size_t)(b * NCHUNK + chunk)) * S_ * D_;
#pragma unroll
        for (int s = 0; s < 8; s++) {
            float4 cmb = *(const float4*)&qk_s[s * D_ + d4];
            cmb.x += acc8[s].x; cmb.y += acc8[s].y;
            cmb.z += acc8[s].z; cmb.w += acc8[s].w;
            float A = A_s[s], G = G_s[s];
            float4 o;
            o.x = w4.x * (cmb.x - G) + b4.x * A;
            o.y = w4.y * (cmb.y - G) + b4.y * A;
            o.z = w4.z * (cmb.z - G) + b4.z * A;
            o.w = w4.w * (cmb.w - G) + b4.w * A;
            *(float4*)(&g_Upart[base + s * D_ + d4]) = o;
        }
    }
}

// deterministic reduction of partials + rowsum normalization
__global__ void reduce_updates_kernel() {
    int bs = blockIdx.x;           // b*8+s
    int b = bs >> 3, s = bs & 7;
    int d = threadIdx.x;           // 512 threads
    float rs = 0.f;
#pragma unroll
    for (int c = 0; c < NCHUNK; c++) rs += g_rspart[(b * NCHUNK + c) * 8 + s];
    float acc = 0.f;
    for (int c = 0; c < NCHUNK; c++)
        acc += g_Upart[(((size_t)(b * NCHUNK + c)) * S_ + s) * D_ + d];
    g_updates[(size_t)bs * D_ + d] = acc / rs;
}

// -------------------- host orchestration -----------------------------------
extern "C" void kernel_launch(void* const* d_in, const int* in_sizes, int n_in,
                              void* d_out, int out_size) {
    const float* slots_in = (const float*)d_in[0];
    const float* features = (const float*)d_in[1];
    const float* w_k      = (const float*)d_in[2];
    const float* w_v      = (const float*)d_in[3];
    const float* w_q      = (const float*)d_in[4];
    const float* ln_feat_w = (const float*)d_in[5];
    const float* ln_feat_b = (const float*)d_in[6];
    const float* ln_slot_w = (const float*)d_in[7];
    const float* ln_slot_b = (const float*)d_in[8];
    const float* gru_w_ih = (const float*)d_in[9];
    const float* gru_w_hh = (const float*)d_in[10];
    const float* gru_b_ih = (const float*)d_in[11];
    const float* gru_b_hh = (const float*)d_in[12];
    const float* ln_mlp_w = (const float*)d_in[13];
    const float* ln_mlp_b = (const float*)d_in[14];
    const float* mlp_w1   = (const float*)d_in[15];
    const float* mlp_b1   = (const float*)d_in[16];
    const float* mlp_w2   = (const float*)d_in[17];
    const float* mlp_b2   = (const float*)d_in[18];

    float* out = (float*)d_out;
    float* out_slots = out;                      // [32,8,512]
    float* out_attn  = out + B_ * S_ * D_;       // [32,8,4096]

    float *p_Wqkhh, *p_bias2048, *p_Wvih, *p_sn, *p_qkgh, *p_gi,
          *p_updates, *p_mlpin, *p_hbuf, *p_split;
    cudaGetSymbolAddress((void**)&p_Wqkhh, g_Wqkhh);
    cudaGetSymbolAddress((void**)&p_bias2048, g_bias2048);
    cudaGetSymbolAddress((void**)&p_Wvih, g_Wvih);
    cudaGetSymbolAddress((void**)&p_sn, g_sn);
    cudaGetSymbolAddress((void**)&p_qkgh, g_qkgh);
    cudaGetSymbolAddress((void**)&p_gi, g_gi);
    cudaGetSymbolAddress((void**)&p_updates, g_updates);
    cudaGetSymbolAddress((void**)&p_mlpin, g_mlpin);
    cudaGetSymbolAddress((void**)&p_hbuf, g_hbuf);
    cudaGetSymbolAddress((void**)&p_split, g_split);

    const int NS = B_ * S_;          // 256 slot rows

    // -------- precomputes --------
    feat_stats_kernel<<<(B_ * F_) / 8, 256>>>(features);
    // Wqk tmp = w_q @ w_k^T  (NT, split-8 Kz=64) -> g_gi tmp
    gemm128_kernel<true><<<dim3(8, 4, 8), 256>>>(w_q, w_k, p_split, D_, D_, D_, D_);
    splitk_reduce<false><<<(512 * 512 / 4 + 255) / 256, 256>>>(nullptr, p_gi,
        512 * 512, 512, 8, 512 * 512);
    // W_vih = w_v @ w_ih^T  (NT, split-4 Kz=128)
    gemm128_kernel<true><<<dim3(24, 4, 4), 256>>>(w_v, gru_w_ih, p_split, D_, 3 * D_, D_, 3 * D_);
    splitk_reduce<false><<<(512 * 1536 / 4 + 255) / 256, 256>>>(nullptr, p_Wvih,
        512 * 1536, 1536, 4, 512 * 1536);
    // pack Wqkhh + bias
    build_whh_kernel<<<(512 * 2048) / 256, 256>>>(gru_w_hh, gru_b_hh, p_gi);

    for (int it = 0; it < NITERS_; it++) {
        bool last = (it == NITERS_ - 1);

        if (it == 0)
            ln_rows_kernel<<<NS, 128>>>(slots_in, p_sn, ln_slot_w, ln_slot_b);

        // [qk | gh] = s_n @ Wqkhh + [0 | b_hh]   (NN, N=2048, split-8 Kz=64)
        gemm128_kernel<false><<<dim3(32, 2, 8), 256>>>(p_sn, p_Wqkhh, p_split,
                                                       NS, 2048, D_, 2048);
        splitk_reduce<false><<<(NS * 2048 / 4 + 255) / 256, 256>>>(p_bias2048, p_qkgh,
            NS * 2048, 2048, 8, NS * 2048);

        // fused attention pass over features
        iter_pass_kernel<<<dim3(NCHUNK, B_), 256>>>(features, ln_feat_w, ln_feat_b,
                                                    last ? out_attn : nullptr);
        reduce_updates_kernel<<<NS, D_>>>();

        // gi partials = updates @ W_vih   (NN, N=1536, split-8 Kz=64)
        gemm128_kernel<false><<<dim3(24, 2, 8), 256>>>(p_updates, p_Wvih, p_split,
                                                       NS, 3 * D_, D_, 3 * D_);
        // fused: gi reduce + b_ih + GRU combine + LN(mlp)
        gru_ln_kernel<<<NS, D_>>>(gru_b_ih, ln_mlp_w, ln_mlp_b);

        // mlp1 = relu(mlpin @ w1 + b1)   (NN, N=2048, split-8 Kz=64)
        gemm128_kernel<false><<<dim3(32, 2, 8), 256>>>(p_mlpin, mlp_w1, p_split,
                                                       NS, H_, D_, H_);
        splitk_reduce<true><<<(NS * 2048 / 4 + 255) / 256, 256>>>(mlp_b1, p_hbuf,
            NS * 2048, 2048, 8, NS * 2048);

        // mlp2 partials (NN, N=512, K=2048, split-16 Kz=128)
        gemm128_kernel<false><<<dim3(8, 2, 16), 256>>>(p_hbuf, mlp_w2, p_split,
                                                       NS, D_, H_, D_);
        // reduce + bias + residual + LN(slot) -> sn (and out_slots if last)
        mlp2_reduce_ln<<<NS, D_>>>(mlp_b2, ln_slot_w, ln_slot_b,
                                   last ? out_slots : nullptr);
    }
}

// round 14
// speedup vs baseline: 1.3425x; 1.1599x over previous
#include <cuda_runtime.h>
#include <math.h>

// ---------------------------------------------------------------------------
// SlotAttention — B=32, F=4096, S=8, D=512, H=2048, 3 iterations.
// K/V never materialized. LN folded out of the feature pass algebraically.
// iter_pass phase 1: q register-resident per warp-group (no smem reads in the
// hot loop). GEMMs: 128x64 tile, 8x4 micro, packed f32x2 FMA (compact B smem).
// Split-K + deterministic fixed-order reduction.
// ---------------------------------------------------------------------------

#define B_ 32
#define F_ 4096
#define S_ 8
#define D_ 512
#define H_ 2048
#define NITERS_ 3
#define CHUNK 128
#define NCHUNK (F_ / CHUNK) /* 32 */

static __device__ __constant__ float kEPS = 1e-8f;
#define LN_EPS 1e-5f
#define SCALE_ 0.04419417382415922f /* 512^-0.5 */

typedef unsigned long long u64t;

// -------------------- packed f32x2 helpers ----------------------------------
__device__ __forceinline__ u64t f2pack(float x, float y) {
    u64t r;
    asm("mov.b64 %0, {%1, %2};" : "=l"(r) : "f"(x), "f"(y));
    return r;
}
__device__ __forceinline__ float2 f2unpack(u64t p) {
    float lo, hi;
    asm("mov.b64 {%0, %1}, %2;" : "=f"(lo), "=f"(hi) : "l"(p));
    return make_float2(lo, hi);
}
__device__ __forceinline__ void f2fma(u64t& d, u64t a, u64t b) {
    asm("fma.rn.f32x2 %0, %1, %2, %0;" : "+l"(d) : "l"(a), "l"(b));
}

// -------------------- scratch (device globals) ------------------------------
__device__ float g_stats[B_ * F_ * 2];
__device__ float g_Wqkhh[D_ * 2048];              // [Wqk | w_hh^T] (512 x 2048)
__device__ float g_bias2048[2048];                // [0 | b_hh]
__device__ float g_Wvih[D_ * 3 * D_];             // w_v @ w_ih^T (512 x 1536)
__device__ float g_sn[B_ * S_ * D_];
__device__ float g_qkgh[B_ * S_ * 2048];          // cols 0-511 qk, 512-2047 gh
__device__ float g_gi[B_ * S_ * 3 * D_];          // reused as Wqk tmp
__device__ float g_updates[B_ * S_ * D_];
__device__ float g_slots2[B_ * S_ * D_];
__device__ float g_mlpin[B_ * S_ * D_];
__device__ float g_hbuf[B_ * S_ * H_];
__device__ float g_split[8 * B_ * S_ * 2048];     // split-K partials (16 MB)
__device__ float g_Upart[B_ * NCHUNK * S_ * D_];  // 16 MB partials
__device__ float g_rspart[B_ * NCHUNK * S_];

// -------------------- small utility kernels --------------------------------
__global__ void feat_stats_kernel(const float* __restrict__ feat) {
    int row = blockIdx.x * 8 + (threadIdx.x >> 5);
    int lane = threadIdx.x & 31;
    const float4* r4 = (const float4*)(feat + (size_t)row * D_);
    float s = 0.f, ss = 0.f;
#pragma unroll
    for (int i = 0; i < 4; i++) {
        float4 v = r4[lane + 32 * i];
        s += v.x + v.y + v.z + v.w;
        ss += v.x * v.x + v.y * v.y + v.z * v.z + v.w * v.w;
    }
#pragma unroll
    for (int o = 16; o; o >>= 1) {
        s += __shfl_xor_sync(0xffffffffu, s, o);
        ss += __shfl_xor_sync(0xffffffffu, ss, o);
    }
    if (lane == 0) {
        float m = s * (1.f / D_);
        float var = ss * (1.f / D_) - m * m;
        g_stats[row * 2] = m;
        g_stats[row * 2 + 1] = rsqrtf(fmaxf(var, 0.f) + LN_EPS);
    }
}

// LayerNorm of [R, 512] rows -> Y (128 threads per row) — used only at iter 0
__global__ void ln_rows_kernel(const float* __restrict__ X, float* __restrict__ Y,
                               const float* __restrict__ w, const float* __restrict__ b) {
    __shared__ float red[48];
    int row = blockIdx.x;
    const float* x = X + (size_t)row * D_;
    int t = threadIdx.x;
    float v[4];
    float s = 0.f, ss = 0.f;
#pragma unroll
    for (int i = 0; i < 4; i++) {
        v[i] = x[t + 128 * i];
        s += v[i];
        ss += v[i] * v[i];
    }
#pragma unroll
    for (int o = 16; o; o >>= 1) {
        s += __shfl_xor_sync(0xffffffffu, s, o);
        ss += __shfl_xor_sync(0xffffffffu, ss, o);
    }
    int warp = t >> 5, lane = t & 31;
    if (lane == 0) { red[warp] = s; red[warp + 8] = ss; }
    __syncthreads();
    if (t == 0) {
        float S2 = 0.f, SS = 0.f;
        for (int wi = 0; wi < 4; wi++) { S2 += red[wi]; SS += red[wi + 8]; }
        float m = S2 * (1.f / D_);
        red[16] = m;
        red[17] = rsqrtf(fmaxf(SS * (1.f / D_) - m * m, 0.f) + LN_EPS);
    }
    __syncthreads();
    float m = red[16], r = red[17];
    float* y = Y + (size_t)row * D_;
#pragma unroll
    for (int i = 0; i < 4; i++) {
        int d = t + 128 * i;
        y[d] = (v[i] - m) * r * w[d] + b[d];
    }
}

// pack Wqkhh = [Wqk(from tmp) | w_hh^T]; bias2048 = [0 | b_hh]
__global__ void build_whh_kernel(const float* __restrict__ w_hh,
                                 const float* __restrict__ b_hh,
                                 const float* __restrict__ wqk_tmp) {
    int idx = blockIdx.x * 256 + threadIdx.x;   // < 512*2048
    int d = idx >> 11, col = idx & 2047;
    g_Wqkhh[idx] = (col < 512) ? wqk_tmp[(size_t)d * 512 + col]
                               : w_hh[(size_t)(col - 512) * 512 + d];
    if (idx < 2048) g_bias2048[idx] = (idx < 512) ? 0.f : b_hh[idx - 512];
}

// -------------------- SGEMM: 128x64x16 tiles, 256 threads, 8x4 micro --------
// Accumulators packed f32x2 along M (A-pairs free from LDS.128 of k-major As).
// Compact B smem (R11-proven). Double-buffered. Split-K slabs.
template <bool TRANS_B>
__global__ void __launch_bounds__(256, 3)
gemm128_kernel(const float* __restrict__ A, const float* __restrict__ Bm,
               float* __restrict__ C, int M, int N, int K, int ldc) {
    __shared__ __align__(16) float As[2][16][128];
    __shared__ __align__(16) float Bs[2][16][64];
    const int tid = threadIdx.x;          // 256 threads
    const int bm = blockIdx.y * 128;
    const int bn = blockIdx.x * 64;
    const int Kz = K / gridDim.z;
    const int kbase = blockIdx.z * Kz;
    C += (size_t)blockIdx.z * M * ldc;

    const int tx = tid & 15, ty = tid >> 4;   // micro: 8 rows (4 pairs) x 4 cols
    const int a_m0 = tid >> 2;                // 0..63
    const int a_k  = (tid & 3) * 4;
    const int b_k = tid >> 4, b_n = (tid & 15) * 4;
    const int bt_n = tid >> 2;                // 0..63

    float4 pa0, pa1, pb;
    u64t acc[4][4];
#pragma unroll
    for (int i = 0; i < 4; i++)
#pragma unroll
        for (int j = 0; j < 4; j++) acc[i][j] = 0ull;

    const int nsteps = Kz / 16;

    pa0 = *(const float4*)(A + (size_t)(bm + a_m0) * K + kbase + a_k);
    pa1 = *(const float4*)(A + (size_t)(bm + a_m0 + 64) * K + kbase + a_k);
    if (TRANS_B)
        pb = *(const float4*)(Bm + (size_t)(bn + bt_n) * K + kbase + a_k);
    else
        pb = *(const float4*)(Bm + (size_t)(kbase + b_k) * N + bn + b_n);

    As[0][a_k + 0][a_m0] = pa0.x; As[0][a_k + 1][a_m0] = pa0.y;
    As[0][a_k + 2][a_m0] = pa0.z; As[0][a_k + 3][a_m0] = pa0.w;
    As[0][a_k + 0][a_m0 + 64] = pa1.x; As[0][a_k + 1][a_m0 + 64] = pa1.y;
    As[0][a_k + 2][a_m0 + 64] = pa1.z; As[0][a_k + 3][a_m0 + 64] = pa1.w;
    if (TRANS_B) {
        Bs[0][a_k + 0][bt_n] = pb.x; Bs[0][a_k + 1][bt_n] = pb.y;
        Bs[0][a_k + 2][bt_n] = pb.z; Bs[0][a_k + 3][bt_n] = pb.w;
    } else {
        *(float4*)&Bs[0][b_k][b_n] = pb;
    }
    __syncthreads();

    int buf = 0;
    for (int s = 0; s < nsteps; s++) {
        if (s + 1 < nsteps) {
            int kb = kbase + (s + 1) * 16;
            pa0 = *(const float4*)(A + (size_t)(bm + a_m0) * K + kb + a_k);
            pa1 = *(const float4*)(A + (size_t)(bm + a_m0 + 64) * K + kb + a_k);
            if (TRANS_B)
                pb = *(const float4*)(Bm + (size_t)(bn + bt_n) * K + kb + a_k);
            else
                pb = *(const float4*)(Bm + (size_t)(kb + b_k) * N + bn + b_n);
        }
#pragma unroll
        for (int k = 0; k < 16; k++) {
            const ulonglong2 ap01 = *(const ulonglong2*)&As[buf][k][ty * 8];
            const ulonglong2 ap23 = *(const ulonglong2*)&As[buf][k][ty * 8 + 4];
            const float4 b4 = *(const float4*)&Bs[buf][k][tx * 4];
            u64t ap[4] = {ap01.x, ap01.y, ap23.x, ap23.y};
            u64t bd[4];
            bd[0] = f2pack(b4.x, b4.x); bd[1] = f2pack(b4.y, b4.y);
            bd[2] = f2pack(b4.z, b4.z); bd[3] = f2pack(b4.w, b4.w);
#pragma unroll
            for (int i = 0; i < 4; i++)
#pragma unroll
                for (int j = 0; j < 4; j++) f2fma(acc[i][j], ap[i], bd[j]);
        }
        if (s + 1 < nsteps) {
            int nb = buf ^ 1;
            As[nb][a_k + 0][a_m0] = pa0.x; As[nb][a_k + 1][a_m0] = pa0.y;
            As[nb][a_k + 2][a_m0] = pa0.z; As[nb][a_k + 3][a_m0] = pa0.w;
            As[nb][a_k + 0][a_m0 + 64] = pa1.x; As[nb][a_k + 1][a_m0 + 64] = pa1.y;
            As[nb][a_k + 2][a_m0 + 64] = pa1.z; As[nb][a_k + 3][a_m0 + 64] = pa1.w;
            if (TRANS_B) {
                Bs[nb][a_k + 0][bt_n] = pb.x; Bs[nb][a_k + 1][bt_n] = pb.y;
                Bs[nb][a_k + 2][bt_n] = pb.z; Bs[nb][a_k + 3][bt_n] = pb.w;
            } else {
                *(float4*)&Bs[nb][b_k][b_n] = pb;
            }
            __syncthreads();
            buf = nb;
        }
    }
#pragma unroll
    for (int i2 = 0; i2 < 4; i2++) {
        float2 c0 = f2unpack(acc[i2][0]), c1 = f2unpack(acc[i2][1]);
        float2 c2 = f2unpack(acc[i2][2]), c3 = f2unpack(acc[i2][3]);
        int r0 = bm + ty * 8 + 2 * i2;
        *(float4*)(C + (size_t)r0 * ldc + bn + tx * 4) =
            make_float4(c0.x, c1.x, c2.x, c3.x);
        *(float4*)(C + (size_t)(r0 + 1) * ldc + bn + tx * 4) =
            make_float4(c0.y, c1.y, c2.y, c3.y);
    }
}

// deterministic split-K reduce (float4): out contiguous (ldo == ncols)
template <bool RELU>
__global__ void splitk_reduce(const float* __restrict__ bias, float* __restrict__ out,
                              int n, int ncols, int nsplit, int stride) {
    int i = (blockIdx.x * 256 + threadIdx.x) * 4;
    if (i >= n) return;
    float4 v = make_float4(0.f, 0.f, 0.f, 0.f);
    for (int z = 0; z < nsplit; z++) {
        const float4 p = *(const float4*)(g_split + (size_t)z * stride + i);
        v.x += p.x; v.y += p.y; v.z += p.z; v.w += p.w;
    }
    if (bias) {
        int col = i % ncols;
        const float4 bq = *(const float4*)(bias + col);
        v.x += bq.x; v.y += bq.y; v.z += bq.z; v.w += bq.w;
    }
    if (RELU) {
        v.x = fmaxf(v.x, 0.f); v.y = fmaxf(v.y, 0.f);
        v.z = fmaxf(v.z, 0.f); v.w = fmaxf(v.w, 0.f);
    }
    *(float4*)(out + i) = v;
}

// -------------------- fused row kernels (512 threads = 1 row) ---------------
__device__ __forceinline__ void block_ln_512(float v, float* red, int t,
                                             float& m_out, float& r_out) {
    float s = v, ss = v * v;
#pragma unroll
    for (int o = 16; o; o >>= 1) {
        s += __shfl_xor_sync(0xffffffffu, s, o);
        ss += __shfl_xor_sync(0xffffffffu, ss, o);
    }
    int warp = t >> 5, lane = t & 31;
    if (lane == 0) { red[warp] = s; red[warp + 16] = ss; }
    __syncthreads();
    if (t == 0) {
        float S2 = 0.f, SS = 0.f;
#pragma unroll
        for (int wi = 0; wi < 16; wi++) { S2 += red[wi]; SS += red[wi + 16]; }
        float m = S2 * (1.f / D_);
        red[32] = m;
        red[33] = rsqrtf(fmaxf(SS * (1.f / D_) - m * m, 0.f) + LN_EPS);
    }
    __syncthreads();
    m_out = red[32];
    r_out = red[33];
}

// gi split-8 reduce + GRU combine + LN(ln_mlp) -> slots2, mlpin.
__global__ void gru_ln_kernel(const float* __restrict__ b_ih,
                              const float* __restrict__ lnw, const float* __restrict__ lnb) {
    __shared__ float red[34];
    int r = blockIdx.x, d = threadIdx.x;
    float ir = b_ih[d], iz = b_ih[D_ + d], in_ = b_ih[2 * D_ + d];
    size_t base = (size_t)r * 3 * D_ + d;
#pragma unroll
    for (int zz = 0; zz < 8; zz++) {
        const float* sl = g_split + (size_t)zz * (B_ * S_ * 3 * D_);
        ir  += sl[base];
        iz  += sl[base + D_];
        in_ += sl[base + 2 * D_];
    }
    size_t ghb = (size_t)r * 2048 + 512;
    float hr = g_qkgh[ghb + d], hz = g_qkgh[ghb + D_ + d], hn = g_qkgh[ghb + 2 * D_ + d];
    float rg = 1.f / (1.f + expf(-(ir + hr)));
    float z  = 1.f / (1.f + expf(-(iz + hz)));
    float n  = tanhf(in_ + rg * hn);
    float v  = (1.f - z) * n + z * g_sn[(size_t)r * D_ + d];
    g_slots2[(size_t)r * D_ + d] = v;
    float m, rs;
    block_ln_512(v, red, d, m, rs);
    g_mlpin[(size_t)r * D_ + d] = (v - m) * rs * lnw[d] + lnb[d];
}

// mlp2 split-16 reduce + b2 + residual(slots2) + LN(ln_slot) -> sn (+out last)
__global__ void mlp2_reduce_ln(const float* __restrict__ b2,
                               const float* __restrict__ lnw, const float* __restrict__ lnb,
                               float* __restrict__ out_slots /* null unless last */) {
    __shared__ float red[34];
    int r = blockIdx.x, d = threadIdx.x;
    size_t i = (size_t)r * D_ + d;
    float v = b2[d] + g_slots2[i];
#pragma unroll
    for (int z = 0; z < 16; z++) v += g_split[(size_t)z * (B_ * S_ * D_) + i];
    if (out_slots) out_slots[i] = v;
    float m, rs;
    block_ln_512(v, red, d, m, rs);
    g_sn[i] = (v - m) * rs * lnw[d] + lnb[d];
}

// -------------------- fused per-iteration feature pass ----------------------
// LN folded out: dots = rstd*(x.wq - mean*swq) + cq ;  U = w*(sum(beta*x)-G)+b*A
// Phase 1: warps 0-3 handle slots 0-3, warps 4-7 slots 4-7; q in registers.
__global__ void iter_pass_kernel(const float* __restrict__ feat,
                                 const float* __restrict__ lnw,
                                 const float* __restrict__ lnb,
                                 float* __restrict__ attn_out) {
    __shared__ __align__(16) float qk_s[S_ * D_];  // wq; reused as reduce buffer
    __shared__ __align__(16) float dots_s[CHUNK * S_];
    __shared__ __align__(16) float attn_s[CHUNK * S_];
    __shared__ __align__(16) u64t betasd_s[CHUNK * S_];   // duplicated (b,b)
    __shared__ __align__(16) float lnw_s[D_], lnb_s[D_];
    __shared__ float stats_s[CHUNK * 2];
    __shared__ float wsum_s[4][8], gsum_s[4][8];
    __shared__ float swq_s[8], cq_s[8], A_s[8], G_s[8];

    int chunk = blockIdx.x, b = blockIdx.y;
    int tid = threadIdx.x, warp = tid >> 5, lane = tid & 31;
    int f0 = chunk * CHUNK;

    for (int i = tid; i < D_; i += 256) { lnw_s[i] = lnw[i]; lnb_s[i] = lnb[i]; }
    for (int i = tid; i < CHUNK * 2; i += 256) stats_s[i] = g_stats[((size_t)b * F_ + f0) * 2 + i];
    __syncthreads();

    // ---- per-warp wq prep: warp w handles slot s=w ----
    {
        int s = warp;
        const float* qrow = g_qkgh + ((size_t)(b * 8 + s)) * 2048;
        float swq = 0.f, cq = 0.f;
#pragma unroll
        for (int i = 0; i < 4; i++) {
            int d4 = (lane + 32 * i) * 4;
            float4 q = *(const float4*)(qrow + d4);
            float4 w4 = *(const float4*)&lnw_s[d4];
            float4 b4 = *(const float4*)&lnb_s[d4];
            float4 wq = make_float4(q.x * w4.x, q.y * w4.y, q.z * w4.z, q.w * w4.w);
            *(float4*)&qk_s[s * D_ + d4] = wq;
            swq += wq.x + wq.y + wq.z + wq.w;
            cq  += b4.x * q.x + b4.y * q.y + b4.z * q.z + b4.w * q.w;
        }
#pragma unroll
        for (int o = 16; o; o >>= 1) {
            swq += __shfl_xor_sync(0xffffffffu, swq, o);
            cq  += __shfl_xor_sync(0xffffffffu, cq, o);
        }
        if (lane == 0) { swq_s[s] = swq; cq_s[s] = cq; }
    }
    __syncthreads();

    // ---- phase 1: register-resident q; warp group g covers slots g*4..g*4+3
    {
        const int g = warp >> 2;
        const int sp0 = g * 4;
        u64t qreg[4][8];   // [slot][pair] — lane's 16 dims x 4 slots
#pragma unroll
        for (int s = 0; s < 4; s++)
#pragma unroll
            for (int i = 0; i < 4; i++) {
                const ulonglong2 qp =
                    *(const ulonglong2*)&qk_s[(sp0 + s) * D_ + (lane + 32 * i) * 4];
                qreg[s][2 * i] = qp.x;
                qreg[s][2 * i + 1] = qp.y;
            }
        for (int fl = (warp & 3); fl < CHUNK; fl += 4) {
            const ulonglong2* r2p =
                (const ulonglong2*)(feat + ((size_t)(b * F_ + f0 + fl)) * D_);
            u64t acc4[4] = {};
#pragma unroll
            for (int i = 0; i < 4; i++) {
                const ulonglong2 xv = r2p[lane + 32 * i];
#pragma unroll
                for (int s = 0; s < 4; s++) {
                    f2fma(acc4[s], xv.x, qreg[s][2 * i]);
                    f2fma(acc4[s], xv.y, qreg[s][2 * i + 1]);
                }
            }
            float a[4];
#pragma unroll
            for (int s = 0; s < 4; s++) {
                float2 u = f2unpack(acc4[s]);
                a[s] = u.x + u.y;
            }
            // fold-reduce: lane l ends with full dot of slot sp0 + ((l>>3)&3)
            float r2v[2];
#pragma unroll
            for (int s = 0; s < 2; s++) {
                float mine  = (lane & 16) ? a[s + 2] : a[s];
                float other = (lane & 16) ? a[s] : a[s + 2];
                r2v[s] = mine + __shfl_xor_sync(0xffffffffu, other, 16);
            }
            float mine  = (lane & 8) ? r2v[1] : r2v[0];
            float other = (lane & 8) ? r2v[0] : r2v[1];
            float r1 = mine + __shfl_xor_sync(0xffffffffu, other, 8);
            r1 += __shfl_xor_sync(0xffffffffu, r1, 4);
            r1 += __shfl_xor_sync(0xffffffffu, r1, 2);
            r1 += __shfl_xor_sync(0xffffffffu, r1, 1);
            if ((lane & 7) == 0)
                dots_s[fl * 8 + sp0 + ((lane >> 3) & 3)] = r1;
        }
    }
    __syncthreads();

    // ---- softmax stage: threads 0-127, one row each ----
    if (tid < 128) {
        int fl = tid;
        const float4 d0 = *(const float4*)&dots_s[fl * 8];
        const float4 d1 = *(const float4*)&dots_s[fl * 8 + 4];
        float dv[8] = {d0.x, d0.y, d0.z, d0.w, d1.x, d1.y, d1.z, d1.w};
        float mean = stats_s[fl * 2], rstd = stats_s[fl * 2 + 1];
        float sc[8], mx;
#pragma unroll
        for (int s = 0; s < 8; s++)
            sc[s] = (rstd * (dv[s] - mean * swq_s[s]) + cq_s[s]) * SCALE_;
        mx = sc[0];
#pragma unroll
        for (int s = 1; s < 8; s++) mx = fmaxf(mx, sc[s]);
        float e[8], den = 0.f;
#pragma unroll
        for (int s = 0; s < 8; s++) { e[s] = expf(sc[s] - mx); den += e[s]; }
        float inv = 1.f / den;
        float wsum8[8], gsum8[8];
#pragma unroll
        for (int s = 0; s < 8; s++) {
            float p = e[s] * inv;
            attn_s[fl * 8 + s] = p;
            float al = p + kEPS;
            float bt = al * rstd;
            betasd_s[fl * 8 + s] = f2pack(bt, bt);
            wsum8[s] = al;
            gsum8[s] = bt * mean;
        }
        // reduce across 32 rows within each of warps 0-3
#pragma unroll
        for (int s = 0; s < 8; s++) {
#pragma unroll
            for (int o = 16; o; o >>= 1) {
                wsum8[s] += __shfl_xor_sync(0xffffffffu, wsum8[s], o);
                gsum8[s] += __shfl_xor_sync(0xffffffffu, gsum8[s], o);
            }
        }
        if (lane == 0) {
#pragma unroll
            for (int s = 0; s < 8; s++) { wsum_s[warp][s] = wsum8[s]; gsum_s[warp][s] = gsum8[s]; }
        }
    }
    __syncthreads();
    if (tid < 8) {
        float tA = 0.f, tG = 0.f;
#pragma unroll
        for (int w = 0; w < 4; w++) { tA += wsum_s[w][tid]; tG += gsum_s[w][tid]; }
        g_rspart[(b * NCHUNK + chunk) * 8 + tid] = tA;
        A_s[tid] = tA;
        G_s[tid] = tG;
    }
    if (attn_out) {
        for (int idx = tid; idx < CHUNK * S_; idx += 256) {
            int s = idx >> 7;
            int fl = idx & 127;
            attn_out[((size_t)(b * S_ + s)) * F_ + f0 + fl] = attn_s[fl * 8 + s];
        }
    }

    // ---- phase 2: sum(beta*x); x pairs free from LDG, betas dup from LDS ----
    int half = tid >> 7;              // 0: rows 0-63, 1: rows 64-127
    int d4 = (tid & 127) * 4;
    float4 w4 = *(const float4*)&lnw_s[d4];
    float4 b4 = *(const float4*)&lnb_s[d4];
    u64t accp2[2][8];                 // [col-pair][slot]
#pragma unroll
    for (int c = 0; c < 2; c++)
#pragma unroll
        for (int s = 0; s < 8; s++) accp2[c][s] = 0ull;

    int fl0 = half * 64;
    for (int fl = fl0; fl < fl0 + 64; fl++) {
        const ulonglong2 xv = *(const ulonglong2*)(feat + ((size_t)(b * F_ + f0 + fl)) * D_ + d4);
        const ulonglong2 bd01 = *(const ulonglong2*)&betasd_s[fl * 8];
        const ulonglong2 bd23 = *(const ulonglong2*)&betasd_s[fl * 8 + 2];
        const ulonglong2 bd45 = *(const ulonglong2*)&betasd_s[fl * 8 + 4];
        const ulonglong2 bd67 = *(const ulonglong2*)&betasd_s[fl * 8 + 6];
        u64t bd[8] = {bd01.x, bd01.y, bd23.x, bd23.y, bd45.x, bd45.y, bd67.x, bd67.y};
#pragma unroll
        for (int s = 0; s < 8; s++) {
            f2fma(accp2[0][s], xv.x, bd[s]);
            f2fma(accp2[1][s], xv.y, bd[s]);
        }
    }
    float4 acc8[8];
#pragma unroll
    for (int s = 0; s < 8; s++) {
        float2 u0 = f2unpack(accp2[0][s]);
        float2 u1 = f2unpack(accp2[1][s]);
        acc8[s] = make_float4(u0.x, u0.y, u1.x, u1.y);
    }
    __syncthreads();     // phase-1/softmax reads of qk_s done; reuse as buffer
    if (half == 0) {
#pragma unroll
        for (int s = 0; s < 8; s++) *(float4*)&qk_s[s * D_ + d4] = acc8[s];
    }
    __syncthreads();
    if (half == 1) {
        size_t base = ((size_t)(b * NCHUNK + chunk)) * S_ * D_;
#pragma unroll
        for (int s = 0; s < 8; s++) {
            float4 cmb = *(const float4*)&qk_s[s * D_ + d4];
            cmb.x += acc8[s].x; cmb.y += acc8[s].y;
            cmb.z += acc8[s].z; cmb.w += acc8[s].w;
            float A = A_s[s], G = G_s[s];
            float4 o;
            o.x = w4.x * (cmb.x - G) + b4.x * A;
            o.y = w4.y * (cmb.y - G) + b4.y * A;
            o.z = w4.z * (cmb.z - G) + b4.z * A;
            o.w = w4.w * (cmb.w - G) + b4.w * A;
            *(float4*)(&g_Upart[base + s * D_ + d4]) = o;
        }
    }
}

// deterministic reduction of partials + rowsum normalization
__global__ void reduce_updates_kernel() {
    int bs = blockIdx.x;           // b*8+s
    int b = bs >> 3, s = bs & 7;
    int d = threadIdx.x;           // 512 threads
    float rs = 0.f;
#pragma unroll
    for (int c = 0; c < NCHUNK; c++) rs += g_rspart[(b * NCHUNK + c) * 8 + s];
    float acc = 0.f;
    for (int c = 0; c < NCHUNK; c++)
        acc += g_Upart[(((size_t)(b * NCHUNK + c)) * S_ + s) * D_ + d];
    g_updates[(size_t)bs * D_ + d] = acc / rs;
}

// -------------------- host orchestration -----------------------------------
extern "C" void kernel_launch(void* const* d_in, const int* in_sizes, int n_in,
                              void* d_out, int out_size) {
    const float* slots_in = (const float*)d_in[0];
    const float* features = (const float*)d_in[1];
    const float* w_k      = (const float*)d_in[2];
    const float* w_v      = (const float*)d_in[3];
    const float* w_q      = (const float*)d_in[4];
    const float* ln_feat_w = (const float*)d_in[5];
    const float* ln_feat_b = (const float*)d_in[6];
    const float* ln_slot_w = (const float*)d_in[7];
    const float* ln_slot_b = (const float*)d_in[8];
    const float* gru_w_ih = (const float*)d_in[9];
    const float* gru_w_hh = (const float*)d_in[10];
    const float* gru_b_ih = (const float*)d_in[11];
    const float* gru_b_hh = (const float*)d_in[12];
    const float* ln_mlp_w = (const float*)d_in[13];
    const float* ln_mlp_b = (const float*)d_in[14];
    const float* mlp_w1   = (const float*)d_in[15];
    const float* mlp_b1   = (const float*)d_in[16];
    const float* mlp_w2   = (const float*)d_in[17];
    const float* mlp_b2   = (const float*)d_in[18];

    float* out = (float*)d_out;
    float* out_slots = out;                      // [32,8,512]
    float* out_attn  = out + B_ * S_ * D_;       // [32,8,4096]

    float *p_Wqkhh, *p_bias2048, *p_Wvih, *p_sn, *p_qkgh, *p_gi,
          *p_updates, *p_mlpin, *p_hbuf, *p_split;
    cudaGetSymbolAddress((void**)&p_Wqkhh, g_Wqkhh);
    cudaGetSymbolAddress((void**)&p_bias2048, g_bias2048);
    cudaGetSymbolAddress((void**)&p_Wvih, g_Wvih);
    cudaGetSymbolAddress((void**)&p_sn, g_sn);
    cudaGetSymbolAddress((void**)&p_qkgh, g_qkgh);
    cudaGetSymbolAddress((void**)&p_gi, g_gi);
    cudaGetSymbolAddress((void**)&p_updates, g_updates);
    cudaGetSymbolAddress((void**)&p_mlpin, g_mlpin);
    cudaGetSymbolAddress((void**)&p_hbuf, g_hbuf);
    cudaGetSymbolAddress((void**)&p_split, g_split);

    const int NS = B_ * S_;          // 256 slot rows

    // -------- precomputes --------
    feat_stats_kernel<<<(B_ * F_) / 8, 256>>>(features);
    // Wqk tmp = w_q @ w_k^T  (NT, split-8 Kz=64) -> g_gi tmp
    gemm128_kernel<true><<<dim3(8, 4, 8), 256>>>(w_q, w_k, p_split, D_, D_, D_, D_);
    splitk_reduce<false><<<(512 * 512 / 4 + 255) / 256, 256>>>(nullptr, p_gi,
        512 * 512, 512, 8, 512 * 512);
    // W_vih = w_v @ w_ih^T  (NT, split-4 Kz=128)
    gemm128_kernel<true><<<dim3(24, 4, 4), 256>>>(w_v, gru_w_ih, p_split, D_, 3 * D_, D_, 3 * D_);
    splitk_reduce<false><<<(512 * 1536 / 4 + 255) / 256, 256>>>(nullptr, p_Wvih,
        512 * 1536, 1536, 4, 512 * 1536);
    // pack Wqkhh + bias
    build_whh_kernel<<<(512 * 2048) / 256, 256>>>(gru_w_hh, gru_b_hh, p_gi);

    for (int it = 0; it < NITERS_; it++) {
        bool last = (it == NITERS_ - 1);

        if (it == 0)
            ln_rows_kernel<<<NS, 128>>>(slots_in, p_sn, ln_slot_w, ln_slot_b);

        // [qk | gh] = s_n @ Wqkhh + [0 | b_hh]   (NN, N=2048, split-8 Kz=64)
        gemm128_kernel<false><<<dim3(32, 2, 8), 256>>>(p_sn, p_Wqkhh, p_split,
                                                       NS, 2048, D_, 2048);
        splitk_reduce<false><<<(NS * 2048 / 4 + 255) / 256, 256>>>(p_bias2048, p_qkgh,
            NS * 2048, 2048, 8, NS * 2048);

        // fused attention pass over features
        iter_pass_kernel<<<dim3(NCHUNK, B_), 256>>>(features, ln_feat_w, ln_feat_b,
                                                    last ? out_attn : nullptr);
        reduce_updates_kernel<<<NS, D_>>>();

        // gi partials = updates @ W_vih   (NN, N=1536, split-8 Kz=64)
        gemm128_kernel<false><<<dim3(24, 2, 8), 256>>>(p_updates, p_Wvih, p_split,
                                                       NS, 3 * D_, D_, 3 * D_);
        // fused: gi reduce + b_ih + GRU combine + LN(mlp)
        gru_ln_kernel<<<NS, D_>>>(gru_b_ih, ln_mlp_w, ln_mlp_b);

        // mlp1 = relu(mlpin @ w1 + b1)   (NN, N=2048, split-8 Kz=64)
        gemm128_kernel<false><<<dim3(32, 2, 8), 256>>>(p_mlpin, mlp_w1, p_split,
                                                       NS, H_, D_, H_);
        splitk_reduce<true><<<(NS * 2048 / 4 + 255) / 256, 256>>>(mlp_b1, p_hbuf,
            NS * 2048, 2048, 8, NS * 2048);

        // mlp2 partials (NN, N=512, K=2048, split-16 Kz=128)
        gemm128_kernel<false><<<dim3(8, 2, 16), 256>>>(p_hbuf, mlp_w2, p_split,
                                                       NS, D_, H_, D_);
        // reduce + bias + residual + LN(slot) -> sn (and out_slots if last)
        mlp2_reduce_ln<<<NS, D_>>>(mlp_b2, ln_slot_w, ln_slot_b,
                                   last ? out_slots : nullptr);
    }
}

// round 15
// speedup vs baseline: 1.3522x; 1.0072x over previous
#include <cuda_runtime.h>
#include <math.h>

// ---------------------------------------------------------------------------
// SlotAttention — B=32, F=4096, S=8, D=512, H=2048, 3 iterations.
// K/V never materialized. LN folded out of the feature pass algebraically.
// iter_pass phase 1: q register-resident per warp-group (no smem reads in the
// hot loop). GEMMs: 128x64 tile, 8x4 micro, packed f32x2 FMA (compact B smem).
// Split-K + deterministic fixed-order reduction.
// ---------------------------------------------------------------------------

#define B_ 32
#define F_ 4096
#define S_ 8
#define D_ 512
#define H_ 2048
#define NITERS_ 3
#define CHUNK 128
#define NCHUNK (F_ / CHUNK) /* 32 */

static __device__ __constant__ float kEPS = 1e-8f;
#define LN_EPS 1e-5f
#define SCALE_ 0.04419417382415922f /* 512^-0.5 */

typedef unsigned long long u64t;

// -------------------- packed f32x2 helpers ----------------------------------
__device__ __forceinline__ u64t f2pack(float x, float y) {
    u64t r;
    asm("mov.b64 %0, {%1, %2};" : "=l"(r) : "f"(x), "f"(y));
    return r;
}
__device__ __forceinline__ float2 f2unpack(u64t p) {
    float lo, hi;
    asm("mov.b64 {%0, %1}, %2;" : "=f"(lo), "=f"(hi) : "l"(p));
    return make_float2(lo, hi);
}
__device__ __forceinline__ void f2fma(u64t& d, u64t a, u64t b) {
    asm("fma.rn.f32x2 %0, %1, %2, %0;" : "+l"(d) : "l"(a), "l"(b));
}

// -------------------- scratch (device globals) ------------------------------
__device__ float g_stats[B_ * F_ * 2];
__device__ float g_Wqkhh[D_ * 2048];              // [Wqk | w_hh^T] (512 x 2048)
__device__ float g_bias2048[2048];                // [0 | b_hh]
__device__ float g_Wvih[D_ * 3 * D_];             // w_v @ w_ih^T (512 x 1536)
__device__ float g_sn[B_ * S_ * D_];
__device__ float g_qkgh[B_ * S_ * 2048];          // cols 0-511 qk, 512-2047 gh
__device__ float g_gi[B_ * S_ * 3 * D_];          // reused as Wqk tmp
__device__ float g_updates[B_ * S_ * D_];
__device__ float g_slots2[B_ * S_ * D_];
__device__ float g_mlpin[B_ * S_ * D_];
__device__ float g_hbuf[B_ * S_ * H_];
__device__ float g_split[8 * B_ * S_ * 2048];     // split-K partials (16 MB)
__device__ float g_Upart[B_ * NCHUNK * S_ * D_];  // 16 MB partials
__device__ float g_rspart[B_ * NCHUNK * S_];

// -------------------- small utility kernels --------------------------------
__global__ void feat_stats_kernel(const float* __restrict__ feat) {
    int row = blockIdx.x * 8 + (threadIdx.x >> 5);
    int lane = threadIdx.x & 31;
    const float4* r4 = (const float4*)(feat + (size_t)row * D_);
    float s = 0.f, ss = 0.f;
#pragma unroll
    for (int i = 0; i < 4; i++) {
        float4 v = r4[lane + 32 * i];
        s += v.x + v.y + v.z + v.w;
        ss += v.x * v.x + v.y * v.y + v.z * v.z + v.w * v.w;
    }
#pragma unroll
    for (int o = 16; o; o >>= 1) {
        s += __shfl_xor_sync(0xffffffffu, s, o);
        ss += __shfl_xor_sync(0xffffffffu, ss, o);
    }
    if (lane == 0) {
        float m = s * (1.f / D_);
        float var = ss * (1.f / D_) - m * m;
        g_stats[row * 2] = m;
        g_stats[row * 2 + 1] = rsqrtf(fmaxf(var, 0.f) + LN_EPS);
    }
}

// LayerNorm of [R, 512] rows -> Y (128 threads per row) — used only at iter 0
__global__ void ln_rows_kernel(const float* __restrict__ X, float* __restrict__ Y,
                               const float* __restrict__ w, const float* __restrict__ b) {
    __shared__ float red[48];
    int row = blockIdx.x;
    const float* x = X + (size_t)row * D_;
    int t = threadIdx.x;
    float v[4];
    float s = 0.f, ss = 0.f;
#pragma unroll
    for (int i = 0; i < 4; i++) {
        v[i] = x[t + 128 * i];
        s += v[i];
        ss += v[i] * v[i];
    }
#pragma unroll
    for (int o = 16; o; o >>= 1) {
        s += __shfl_xor_sync(0xffffffffu, s, o);
        ss += __shfl_xor_sync(0xffffffffu, ss, o);
    }
    int warp = t >> 5, lane = t & 31;
    if (lane == 0) { red[warp] = s; red[warp + 8] = ss; }
    __syncthreads();
    if (t == 0) {
        float S2 = 0.f, SS = 0.f;
        for (int wi = 0; wi < 4; wi++) { S2 += red[wi]; SS += red[wi + 8]; }
        float m = S2 * (1.f / D_);
        red[16] = m;
        red[17] = rsqrtf(fmaxf(SS * (1.f / D_) - m * m, 0.f) + LN_EPS);
    }
    __syncthreads();
    float m = red[16], r = red[17];
    float* y = Y + (size_t)row * D_;
#pragma unroll
    for (int i = 0; i < 4; i++) {
        int d = t + 128 * i;
        y[d] = (v[i] - m) * r * w[d] + b[d];
    }
}

// pack Wqkhh = [Wqk(from tmp) | w_hh^T]; bias2048 = [0 | b_hh]
__global__ void build_whh_kernel(const float* __restrict__ w_hh,
                                 const float* __restrict__ b_hh,
                                 const float* __restrict__ wqk_tmp) {
    int idx = blockIdx.x * 256 + threadIdx.x;   // < 512*2048
    int d = idx >> 11, col = idx & 2047;
    g_Wqkhh[idx] = (col < 512) ? wqk_tmp[(size_t)d * 512 + col]
                               : w_hh[(size_t)(col - 512) * 512 + d];
    if (idx < 2048) g_bias2048[idx] = (idx < 512) ? 0.f : b_hh[idx - 512];
}

// -------------------- SGEMM: 128x64x16 tiles, 256 threads, 8x4 micro --------
// Accumulators packed f32x2 along M (A-pairs free from LDS.128 of k-major As).
// Compact B smem (R11-proven). Double-buffered. Split-K slabs.
template <bool TRANS_B>
__global__ void __launch_bounds__(256, 3)
gemm128_kernel(const float* __restrict__ A, const float* __restrict__ Bm,
               float* __restrict__ C, int M, int N, int K, int ldc) {
    __shared__ __align__(16) float As[2][16][128];
    __shared__ __align__(16) float Bs[2][16][64];
    const int tid = threadIdx.x;          // 256 threads
    const int bm = blockIdx.y * 128;
    const int bn = blockIdx.x * 64;
    const int Kz = K / gridDim.z;
    const int kbase = blockIdx.z * Kz;
    C += (size_t)blockIdx.z * M * ldc;

    const int tx = tid & 15, ty = tid >> 4;   // micro: 8 rows (4 pairs) x 4 cols
    const int a_m0 = tid >> 2;                // 0..63
    const int a_k  = (tid & 3) * 4;
    const int b_k = tid >> 4, b_n = (tid & 15) * 4;
    const int bt_n = tid >> 2;                // 0..63

    float4 pa0, pa1, pb;
    u64t acc[4][4];
#pragma unroll
    for (int i = 0; i < 4; i++)
#pragma unroll
        for (int j = 0; j < 4; j++) acc[i][j] = 0ull;

    const int nsteps = Kz / 16;

    pa0 = *(const float4*)(A + (size_t)(bm + a_m0) * K + kbase + a_k);
    pa1 = *(const float4*)(A + (size_t)(bm + a_m0 + 64) * K + kbase + a_k);
    if (TRANS_B)
        pb = *(const float4*)(Bm + (size_t)(bn + bt_n) * K + kbase + a_k);
    else
        pb = *(const float4*)(Bm + (size_t)(kbase + b_k) * N + bn + b_n);

    As[0][a_k + 0][a_m0] = pa0.x; As[0][a_k + 1][a_m0] = pa0.y;
    As[0][a_k + 2][a_m0] = pa0.z; As[0][a_k + 3][a_m0] = pa0.w;
    As[0][a_k + 0][a_m0 + 64] = pa1.x; As[0][a_k + 1][a_m0 + 64] = pa1.y;
    As[0][a_k + 2][a_m0 + 64] = pa1.z; As[0][a_k + 3][a_m0 + 64] = pa1.w;
    if (TRANS_B) {
        Bs[0][a_k + 0][bt_n] = pb.x; Bs[0][a_k + 1][bt_n] = pb.y;
        Bs[0][a_k + 2][bt_n] = pb.z; Bs[0][a_k + 3][bt_n] = pb.w;
    } else {
        *(float4*)&Bs[0][b_k][b_n] = pb;
    }
    __syncthreads();

    int buf = 0;
    for (int s = 0; s < nsteps; s++) {
        if (s + 1 < nsteps) {
            int kb = kbase + (s + 1) * 16;
            pa0 = *(const float4*)(A + (size_t)(bm + a_m0) * K + kb + a_k);
            pa1 = *(const float4*)(A + (size_t)(bm + a_m0 + 64) * K + kb + a_k);
            if (TRANS_B)
                pb = *(const float4*)(Bm + (size_t)(bn + bt_n) * K + kb + a_k);
            else
                pb = *(const float4*)(Bm + (size_t)(kb + b_k) * N + bn + b_n);
        }
#pragma unroll
        for (int k = 0; k < 16; k++) {
            const ulonglong2 ap01 = *(const ulonglong2*)&As[buf][k][ty * 8];
            const ulonglong2 ap23 = *(const ulonglong2*)&As[buf][k][ty * 8 + 4];
            const float4 b4 = *(const float4*)&Bs[buf][k][tx * 4];
            u64t ap[4] = {ap01.x, ap01.y, ap23.x, ap23.y};
            u64t bd[4];
            bd[0] = f2pack(b4.x, b4.x); bd[1] = f2pack(b4.y, b4.y);
            bd[2] = f2pack(b4.z, b4.z); bd[3] = f2pack(b4.w, b4.w);
#pragma unroll
            for (int i = 0; i < 4; i++)
#pragma unroll
                for (int j = 0; j < 4; j++) f2fma(acc[i][j], ap[i], bd[j]);
        }
        if (s + 1 < nsteps) {
            int nb = buf ^ 1;
            As[nb][a_k + 0][a_m0] = pa0.x; As[nb][a_k + 1][a_m0] = pa0.y;
            As[nb][a_k + 2][a_m0] = pa0.z; As[nb][a_k + 3][a_m0] = pa0.w;
            As[nb][a_k + 0][a_m0 + 64] = pa1.x; As[nb][a_k + 1][a_m0 + 64] = pa1.y;
            As[nb][a_k + 2][a_m0 + 64] = pa1.z; As[nb][a_k + 3][a_m0 + 64] = pa1.w;
            if (TRANS_B) {
                Bs[nb][a_k + 0][bt_n] = pb.x; Bs[nb][a_k + 1][bt_n] = pb.y;
                Bs[nb][a_k + 2][bt_n] = pb.z; Bs[nb][a_k + 3][bt_n] = pb.w;
            } else {
                *(float4*)&Bs[nb][b_k][b_n] = pb;
            }
            __syncthreads();
            buf = nb;
        }
    }
#pragma unroll
    for (int i2 = 0; i2 < 4; i2++) {
        float2 c0 = f2unpack(acc[i2][0]), c1 = f2unpack(acc[i2][1]);
        float2 c2 = f2unpack(acc[i2][2]), c3 = f2unpack(acc[i2][3]);
        int r0 = bm + ty * 8 + 2 * i2;
        *(float4*)(C + (size_t)r0 * ldc + bn + tx * 4) =
            make_float4(c0.x, c1.x, c2.x, c3.x);
        *(float4*)(C + (size_t)(r0 + 1) * ldc + bn + tx * 4) =
            make_float4(c0.y, c1.y, c2.y, c3.y);
    }
}

// deterministic split-K reduce (float4): out contiguous (ldo == ncols)
template <bool RELU>
__global__ void splitk_reduce(const float* __restrict__ bias, float* __restrict__ out,
                              int n, int ncols, int nsplit, int stride) {
    int i = (blockIdx.x * 256 + threadIdx.x) * 4;
    if (i >= n) return;
    float4 v = make_float4(0.f, 0.f, 0.f, 0.f);
    for (int z = 0; z < nsplit; z++) {
        const float4 p = *(const float4*)(g_split + (size_t)z * stride + i);
        v.x += p.x; v.y += p.y; v.z += p.z; v.w += p.w;
    }
    if (bias) {
        int col = i % ncols;
        const float4 bq = *(const float4*)(bias + col);
        v.x += bq.x; v.y += bq.y; v.z += bq.z; v.w += bq.w;
    }
    if (RELU) {
        v.x = fmaxf(v.x, 0.f); v.y = fmaxf(v.y, 0.f);
        v.z = fmaxf(v.z, 0.f); v.w = fmaxf(v.w, 0.f);
    }
    *(float4*)(out + i) = v;
}

// -------------------- fused row kernels (512 threads = 1 row) ---------------
__device__ __forceinline__ void block_ln_512(float v, float* red, int t,
                                             float& m_out, float& r_out) {
    float s = v, ss = v * v;
#pragma unroll
    for (int o = 16; o; o >>= 1) {
        s += __shfl_xor_sync(0xffffffffu, s, o);
        ss += __shfl_xor_sync(0xffffffffu, ss, o);
    }
    int warp = t >> 5, lane = t & 31;
    if (lane == 0) { red[warp] = s; red[warp + 16] = ss; }
    __syncthreads();
    if (t == 0) {
        float S2 = 0.f, SS = 0.f;
#pragma unroll
        for (int wi = 0; wi < 16; wi++) { S2 += red[wi]; SS += red[wi + 16]; }
        float m = S2 * (1.f / D_);
        red[32] = m;
        red[33] = rsqrtf(fmaxf(SS * (1.f / D_) - m * m, 0.f) + LN_EPS);
    }
    __syncthreads();
    m_out = red[32];
    r_out = red[33];
}

// gi split-8 reduce + GRU combine + LN(ln_mlp) -> slots2, mlpin.
__global__ void gru_ln_kernel(const float* __restrict__ b_ih,
                              const float* __restrict__ lnw, const float* __restrict__ lnb) {
    __shared__ float red[34];
    int r = blockIdx.x, d = threadIdx.x;
    float ir = b_ih[d], iz = b_ih[D_ + d], in_ = b_ih[2 * D_ + d];
    size_t base = (size_t)r * 3 * D_ + d;
#pragma unroll
    for (int zz = 0; zz < 8; zz++) {
        const float* sl = g_split + (size_t)zz * (B_ * S_ * 3 * D_);
        ir  += sl[base];
        iz  += sl[base + D_];
        in_ += sl[base + 2 * D_];
    }
    size_t ghb = (size_t)r * 2048 + 512;
    float hr = g_qkgh[ghb + d], hz = g_qkgh[ghb + D_ + d], hn = g_qkgh[ghb + 2 * D_ + d];
    float rg = 1.f / (1.f + expf(-(ir + hr)));
    float z  = 1.f / (1.f + expf(-(iz + hz)));
    float n  = tanhf(in_ + rg * hn);
    float v  = (1.f - z) * n + z * g_sn[(size_t)r * D_ + d];
    g_slots2[(size_t)r * D_ + d] = v;
    float m, rs;
    block_ln_512(v, red, d, m, rs);
    g_mlpin[(size_t)r * D_ + d] = (v - m) * rs * lnw[d] + lnb[d];
}

// mlp2 split-16 reduce + b2 + residual(slots2) + LN(ln_slot) -> sn (+out last)
__global__ void mlp2_reduce_ln(const float* __restrict__ b2,
                               const float* __restrict__ lnw, const float* __restrict__ lnb,
                               float* __restrict__ out_slots /* null unless last */) {
    __shared__ float red[34];
    int r = blockIdx.x, d = threadIdx.x;
    size_t i = (size_t)r * D_ + d;
    float v = b2[d] + g_slots2[i];
#pragma unroll
    for (int z = 0; z < 16; z++) v += g_split[(size_t)z * (B_ * S_ * D_) + i];
    if (out_slots) out_slots[i] = v;
    float m, rs;
    block_ln_512(v, red, d, m, rs);
    g_sn[i] = (v - m) * rs * lnw[d] + lnb[d];
}

// -------------------- fused per-iteration feature pass ----------------------
// LN folded out: dots = rstd*(x.wq - mean*swq) + cq ;  U = w*(sum(beta*x)-G)+b*A
// Phase 1: warps 0-3 handle slots 0-3, warps 4-7 slots 4-7; q in registers.
__global__ void iter_pass_kernel(const float* __restrict__ feat,
                                 const float* __restrict__ lnw,
                                 const float* __restrict__ lnb,
                                 float* __restrict__ attn_out) {
    __shared__ __align__(16) float qk_s[S_ * D_];  // wq; reused as reduce buffer
    __shared__ __align__(16) float dots_s[CHUNK * S_];
    __shared__ __align__(16) float attn_s[CHUNK * S_];
    __shared__ __align__(16) u64t betasd_s[CHUNK * S_];   // duplicated (b,b)
    __shared__ __align__(16) float lnw_s[D_], lnb_s[D_];
    __shared__ float stats_s[CHUNK * 2];
    __shared__ float wsum_s[4][8], gsum_s[4][8];
    __shared__ float swq_s[8], cq_s[8], A_s[8], G_s[8];

    int chunk = blockIdx.x, b = blockIdx.y;
    int tid = threadIdx.x, warp = tid >> 5, lane = tid & 31;
    int f0 = chunk * CHUNK;

    for (int i = tid; i < D_; i += 256) { lnw_s[i] = lnw[i]; lnb_s[i] = lnb[i]; }
    for (int i = tid; i < CHUNK * 2; i += 256) stats_s[i] = g_stats[((size_t)b * F_ + f0) * 2 + i];
    __syncthreads();

    // ---- per-warp wq prep: warp w handles slot s=w ----
    {
        int s = warp;
        const float* qrow = g_qkgh + ((size_t)(b * 8 + s)) * 2048;
        float swq = 0.f, cq = 0.f;
#pragma unroll
        for (int i = 0; i < 4; i++) {
            int d4 = (lane + 32 * i) * 4;
            float4 q = *(const float4*)(qrow + d4);
            float4 w4 = *(const float4*)&lnw_s[d4];
            float4 b4 = *(const float4*)&lnb_s[d4];
            float4 wq = make_float4(q.x * w4.x, q.y * w4.y, q.z * w4.z, q.w * w4.w);
            *(float4*)&qk_s[s * D_ + d4] = wq;
            swq += wq.x + wq.y + wq.z + wq.w;
            cq  += b4.x * q.x + b4.y * q.y + b4.z * q.z + b4.w * q.w;
        }
#pragma unroll
        for (int o = 16; o; o >>= 1) {
            swq += __shfl_xor_sync(0xffffffffu, swq, o);
            cq  += __shfl_xor_sync(0xffffffffu, cq, o);
        }
        if (lane == 0) { swq_s[s] = swq; cq_s[s] = cq; }
    }
    __syncthreads();

    // ---- phase 1: register-resident q; warp group g covers slots g*4..g*4+3
    {
        const int g = warp >> 2;
        const int sp0 = g * 4;
        u64t qreg[4][8];   // [slot][pair] — lane's 16 dims x 4 slots
#pragma unroll
        for (int s = 0; s < 4; s++)
#pragma unroll
            for (int i = 0; i < 4; i++) {
                const ulonglong2 qp =
                    *(const ulonglong2*)&qk_s[(sp0 + s) * D_ + (lane + 32 * i) * 4];
                qreg[s][2 * i] = qp.x;
                qreg[s][2 * i + 1] = qp.y;
            }
        for (int fl = (warp & 3); fl < CHUNK; fl += 4) {
            const ulonglong2* r2p =
                (const ulonglong2*)(feat + ((size_t)(b * F_ + f0 + fl)) * D_);
            u64t acc4[4] = {};
#pragma unroll
            for (int i = 0; i < 4; i++) {
                const ulonglong2 xv = r2p[lane + 32 * i];
#pragma unroll
                for (int s = 0; s < 4; s++) {
                    f2fma(acc4[s], xv.x, qreg[s][2 * i]);
                    f2fma(acc4[s], xv.y, qreg[s][2 * i + 1]);
                }
            }
            float a[4];
#pragma unroll
            for (int s = 0; s < 4; s++) {
                float2 u = f2unpack(acc4[s]);
                a[s] = u.x + u.y;
            }
            // fold-reduce: lane l ends with full dot of slot sp0 + ((l>>3)&3)
            float r2v[2];
#pragma unroll
            for (int s = 0; s < 2; s++) {
                float mine  = (lane & 16) ? a[s + 2] : a[s];
                float other = (lane & 16) ? a[s] : a[s + 2];
                r2v[s] = mine + __shfl_xor_sync(0xffffffffu, other, 16);
            }
            float mine  = (lane & 8) ? r2v[1] : r2v[0];
            float other = (lane & 8) ? r2v[0] : r2v[1];
            float r1 = mine + __shfl_xor_sync(0xffffffffu, other, 8);
            r1 += __shfl_xor_sync(0xffffffffu, r1, 4);
            r1 += __shfl_xor_sync(0xffffffffu, r1, 2);
            r1 += __shfl_xor_sync(0xffffffffu, r1, 1);
            if ((lane & 7) == 0)
                dots_s[fl * 8 + sp0 + ((lane >> 3) & 3)] = r1;
        }
    }
    __syncthreads();

    // ---- softmax stage: threads 0-127, one row each ----
    if (tid < 128) {
        int fl = tid;
        const float4 d0 = *(const float4*)&dots_s[fl * 8];
        const float4 d1 = *(const float4*)&dots_s[fl * 8 + 4];
        float dv[8] = {d0.x, d0.y, d0.z, d0.w, d1.x, d1.y, d1.z, d1.w};
        float mean = stats_s[fl * 2], rstd = stats_s[fl * 2 + 1];
        float sc[8], mx;
#pragma unroll
        for (int s = 0; s < 8; s++)
            sc[s] = (rstd * (dv[s] - mean * swq_s[s]) + cq_s[s]) * SCALE_;
        mx = sc[0];
#pragma unroll
        for (int s = 1; s < 8; s++) mx = fmaxf(mx, sc[s]);
        float e[8], den = 0.f;
#pragma unroll
        for (int s = 0; s < 8; s++) { e[s] = expf(sc[s] - mx); den += e[s]; }
        float inv = 1.f / den;
        float wsum8[8], gsum8[8];
#pragma unroll
        for (int s = 0; s < 8; s++) {
            float p = e[s] * inv;
            attn_s[fl * 8 + s] = p;
            float al = p + kEPS;
            float bt = al * rstd;
            betasd_s[fl * 8 + s] = f2pack(bt, bt);
            wsum8[s] = al;
            gsum8[s] = bt * mean;
        }
        // reduce across 32 rows within each of warps 0-3
#pragma unroll
        for (int s = 0; s < 8; s++) {
#pragma unroll
            for (int o = 16; o; o >>= 1) {
                wsum8[s] += __shfl_xor_sync(0xffffffffu, wsum8[s], o);
                gsum8[s] += __shfl_xor_sync(0xffffffffu, gsum8[s], o);
            }
        }
        if (lane == 0) {
#pragma unroll
            for (int s = 0; s < 8; s++) { wsum_s[warp][s] = wsum8[s]; gsum_s[warp][s] = gsum8[s]; }
        }
    }
    __syncthreads();
    if (tid < 8) {
        float tA = 0.f, tG = 0.f;
#pragma unroll
        for (int w = 0; w < 4; w++) { tA += wsum_s[w][tid]; tG += gsum_s[w][tid]; }
        g_rspart[(b * NCHUNK + chunk) * 8 + tid] = tA;
        A_s[tid] = tA;
        G_s[tid] = tG;
    }
    if (attn_out) {
        for (int idx = tid; idx < CHUNK * S_; idx += 256) {
            int s = idx >> 7;
            int fl = idx & 127;
            attn_out[((size_t)(b * S_ + s)) * F_ + f0 + fl] = attn_s[fl * 8 + s];
        }
    }

    // ---- phase 2: sum(beta*x); x pairs free from LDG, betas dup from LDS ----
    int half = tid >> 7;              // 0: rows 0-63, 1: rows 64-127
    int d4 = (tid & 127) * 4;
    float4 w4 = *(const float4*)&lnw_s[d4];
    float4 b4 = *(const float4*)&lnb_s[d4];
    u64t accp2[2][8];                 // [col-pair][slot]
#pragma unroll
    for (int c = 0; c < 2; c++)
#pragma unroll
        for (int s = 0; s < 8; s++) accp2[c][s] = 0ull;

    int fl0 = half * 64;
    for (int fl = fl0; fl < fl0 + 64; fl++) {
        const ulonglong2 xv = *(const ulonglong2*)(feat + ((size_t)(b * F_ + f0 + fl)) * D_ + d4);
        const ulonglong2 bd01 = *(const ulonglong2*)&betasd_s[fl * 8];
        const ulonglong2 bd23 = *(const ulonglong2*)&betasd_s[fl * 8 + 2];
        const ulonglong2 bd45 = *(const ulonglong2*)&betasd_s[fl * 8 + 4];
        const ulonglong2 bd67 = *(const ulonglong2*)&betasd_s[fl * 8 + 6];
        u64t bd[8] = {bd01.x, bd01.y, bd23.x, bd23.y, bd45.x, bd45.y, bd67.x, bd67.y};
#pragma unroll
        for (int s = 0; s < 8; s++) {
            f2fma(accp2[0][s], xv.x, bd[s]);
            f2fma(accp2[1][s], xv.y, bd[s]);
        }
    }
    float4 acc8[8];
#pragma unroll
    for (int s = 0; s < 8; s++) {
        float2 u0 = f2unpack(accp2[0][s]);
        float2 u1 = f2unpack(accp2[1][s]);
        acc8[s] = make_float4(u0.x, u0.y, u1.x, u1.y);
    }
    __syncthreads();     // phase-1/softmax reads of qk_s done; reuse as buffer
    if (half == 0) {
#pragma unroll
        for (int s = 0; s < 8; s++) *(float4*)&qk_s[s * D_ + d4] = acc8[s];
    }
    __syncthreads();
    if (half == 1) {
        size_t base = ((size_t)(b * NCHUNK + chunk)) * S_ * D_;
#pragma unroll
        for (int s = 0; s < 8; s++) {
            float4 cmb = *(const float4*)&qk_s[s * D_ + d4];
            cmb.x += acc8[s].x; cmb.y += acc8[s].y;
            cmb.z += acc8[s].z; cmb.w += acc8[s].w;
            float A = A_s[s], G = G_s[s];
            float4 o;
            o.x = w4.x * (cmb.x - G) + b4.x * A;
            o.y = w4.y * (cmb.y - G) + b4.y * A;
            o.z = w4.z * (cmb.z - G) + b4.z * A;
            o.w = w4.w * (cmb.w - G) + b4.w * A;
            *(float4*)(&g_Upart[base + s * D_ + d4]) = o;
        }
    }
}

// deterministic reduction of partials + rowsum normalization
__global__ void reduce_updates_kernel() {
    int bs = blockIdx.x;           // b*8+s
    int b = bs >> 3, s = bs & 7;
    int d = threadIdx.x;           // 512 threads
    float rs = 0.f;
#pragma unroll
    for (int c = 0; c < NCHUNK; c++) rs += g_rspart[(b * NCHUNK + c) * 8 + s];
    float acc = 0.f;
    for (int c = 0; c < NCHUNK; c++)
        acc += g_Upart[(((size_t)(b * NCHUNK + c)) * S_ + s) * D_ + d];
    g_updates[(size_t)bs * D_ + d] = acc / rs;
}

// -------------------- host orchestration -----------------------------------
extern "C" void kernel_launch(void* const* d_in, const int* in_sizes, int n_in,
                              void* d_out, int out_size) {
    const float* slots_in = (const float*)d_in[0];
    const float* features = (const float*)d_in[1];
    const float* w_k      = (const float*)d_in[2];
    const float* w_v      = (const float*)d_in[3];
    const float* w_q      = (const float*)d_in[4];
    const float* ln_feat_w = (const float*)d_in[5];
    const float* ln_feat_b = (const float*)d_in[6];
    const float* ln_slot_w = (const float*)d_in[7];
    const float* ln_slot_b = (const float*)d_in[8];
    const float* gru_w_ih = (const float*)d_in[9];
    const float* gru_w_hh = (const float*)d_in[10];
    const float* gru_b_ih = (const float*)d_in[11];
    const float* gru_b_hh = (const float*)d_in[12];
    const float* ln_mlp_w = (const float*)d_in[13];
    const float* ln_mlp_b = (const float*)d_in[14];
    const float* mlp_w1   = (const float*)d_in[15];
    const float* mlp_b1   = (const float*)d_in[16];
    const float* mlp_w2   = (const float*)d_in[17];
    const float* mlp_b2   = (const float*)d_in[18];

    float* out = (float*)d_out;
    float* out_slots = out;                      // [32,8,512]
    float* out_attn  = out + B_ * S_ * D_;       // [32,8,4096]

    float *p_Wqkhh, *p_bias2048, *p_Wvih, *p_sn, *p_qkgh, *p_gi,
          *p_updates, *p_mlpin, *p_hbuf, *p_split;
    cudaGetSymbolAddress((void**)&p_Wqkhh, g_Wqkhh);
    cudaGetSymbolAddress((void**)&p_bias2048, g_bias2048);
    cudaGetSymbolAddress((void**)&p_Wvih, g_Wvih);
    cudaGetSymbolAddress((void**)&p_sn, g_sn);
    cudaGetSymbolAddress((void**)&p_qkgh, g_qkgh);
    cudaGetSymbolAddress((void**)&p_gi, g_gi);
    cudaGetSymbolAddress((void**)&p_updates, g_updates);
    cudaGetSymbolAddress((void**)&p_mlpin, g_mlpin);
    cudaGetSymbolAddress((void**)&p_hbuf, g_hbuf);
    cudaGetSymbolAddress((void**)&p_split, g_split);

    const int NS = B_ * S_;          // 256 slot rows

    // -------- precomputes --------
    feat_stats_kernel<<<(B_ * F_) / 8, 256>>>(features);
    // Wqk tmp = w_q @ w_k^T  (NT, split-8 Kz=64) -> g_gi tmp
    gemm128_kernel<true><<<dim3(8, 4, 8), 256>>>(w_q, w_k, p_split, D_, D_, D_, D_);
    splitk_reduce<false><<<(512 * 512 / 4 + 255) / 256, 256>>>(nullptr, p_gi,
        512 * 512, 512, 8, 512 * 512);
    // W_vih = w_v @ w_ih^T  (NT, split-4 Kz=128)
    gemm128_kernel<true><<<dim3(24, 4, 4), 256>>>(w_v, gru_w_ih, p_split, D_, 3 * D_, D_, 3 * D_);
    splitk_reduce<false><<<(512 * 1536 / 4 + 255) / 256, 256>>>(nullptr, p_Wvih,
        512 * 1536, 1536, 4, 512 * 1536);
    // pack Wqkhh + bias
    build_whh_kernel<<<(512 * 2048) / 256, 256>>>(gru_w_hh, gru_b_hh, p_gi);

    for (int it = 0; it < NITERS_; it++) {
        bool last = (it == NITERS_ - 1);

        if (it == 0)
            ln_rows_kernel<<<NS, 128>>>(slots_in, p_sn, ln_slot_w, ln_slot_b);

        // [qk | gh] = s_n @ Wqkhh + [0 | b_hh]   (NN, N=2048, split-8 Kz=64)
        gemm128_kernel<false><<<dim3(32, 2, 8), 256>>>(p_sn, p_Wqkhh, p_split,
                                                       NS, 2048, D_, 2048);
        splitk_reduce<false><<<(NS * 2048 / 4 + 255) / 256, 256>>>(p_bias2048, p_qkgh,
            NS * 2048, 2048, 8, NS * 2048);

        // fused attention pass over features
        iter_pass_kernel<<<dim3(NCHUNK, B_), 256>>>(features, ln_feat_w, ln_feat_b,
                                                    last ? out_attn : nullptr);
        reduce_updates_kernel<<<NS, D_>>>();

        // gi partials = updates @ W_vih   (NN, N=1536, split-8 Kz=64)
        gemm128_kernel<false><<<dim3(24, 2, 8), 256>>>(p_updates, p_Wvih, p_split,
                                                       NS, 3 * D_, D_, 3 * D_);
        // fused: gi reduce + b_ih + GRU combine + LN(mlp)
        gru_ln_kernel<<<NS, D_>>>(gru_b_ih, ln_mlp_w, ln_mlp_b);

        // mlp1 = relu(mlpin @ w1 + b1)   (NN, N=2048, split-8 Kz=64)
        gemm128_kernel<false><<<dim3(32, 2, 8), 256>>>(p_mlpin, mlp_w1, p_split,
                                                       NS, H_, D_, H_);
        splitk_reduce<true><<<(NS * 2048 / 4 + 255) / 256, 256>>>(mlp_b1, p_hbuf,
            NS * 2048, 2048, 8, NS * 2048);

        // mlp2 partials (NN, N=512, K=2048, split-16 Kz=128)
        gemm128_kernel<false><<<dim3(8, 2, 16), 256>>>(p_hbuf, mlp_w2, p_split,
                                                       NS, D_, H_, D_);
        // reduce + bias + residual + LN(slot) -> sn (and out_slots if last)
        mlp2_reduce_ln<<<NS, D_>>>(mlp_b2, ln_slot_w, ln_slot_b,
                                   last ? out_slots : nullptr);
    }
}

// round 16
// speedup vs baseline: 1.3538x; 1.0012x over previous
#include <cuda_runtime.h>
#include <math.h>

// ---------------------------------------------------------------------------
// SlotAttention — B=32, F=4096, S=8, D=512, H=2048, 3 iterations.
// K/V never materialized. LN folded out of the feature pass algebraically.
// iter_pass phase 1: q register-resident per warp-group (no smem reads in the
// hot loop). GEMMs: 128x64 tile, 8x4 micro, packed f32x2 FMA (compact B smem).
// Split-K + deterministic fixed-order reduction.
// ---------------------------------------------------------------------------

#define B_ 32
#define F_ 4096
#define S_ 8
#define D_ 512
#define H_ 2048
#define NITERS_ 3
#define CHUNK 128
#define NCHUNK (F_ / CHUNK) /* 32 */

static __device__ __constant__ float kEPS = 1e-8f;
#define LN_EPS 1e-5f
#define SCALE_ 0.04419417382415922f /* 512^-0.5 */

typedef unsigned long long u64t;

// -------------------- packed f32x2 helpers ----------------------------------
__device__ __forceinline__ u64t f2pack(float x, float y) {
    u64t r;
    asm("mov.b64 %0, {%1, %2};" : "=l"(r) : "f"(x), "f"(y));
    return r;
}
__device__ __forceinline__ float2 f2unpack(u64t p) {
    float lo, hi;
    asm("mov.b64 {%0, %1}, %2;" : "=f"(lo), "=f"(hi) : "l"(p));
    return make_float2(lo, hi);
}
__device__ __forceinline__ void f2fma(u64t& d, u64t a, u64t b) {
    asm("fma.rn.f32x2 %0, %1, %2, %0;" : "+l"(d) : "l"(a), "l"(b));
}

// -------------------- scratch (device globals) ------------------------------
__device__ float g_stats[B_ * F_ * 2];
__device__ float g_Wqkhh[D_ * 2048];              // [Wqk | w_hh^T] (512 x 2048)
__device__ float g_bias2048[2048];                // [0 | b_hh]
__device__ float g_Wvih[D_ * 3 * D_];             // w_v @ w_ih^T (512 x 1536)
__device__ float g_sn[B_ * S_ * D_];
__device__ float g_qkgh[B_ * S_ * 2048];          // cols 0-511 qk, 512-2047 gh
__device__ float g_gi[B_ * S_ * 3 * D_];          // reused as Wqk tmp
__device__ float g_updates[B_ * S_ * D_];
__device__ float g_slots2[B_ * S_ * D_];
__device__ float g_mlpin[B_ * S_ * D_];
__device__ float g_hbuf[B_ * S_ * H_];
__device__ float g_split[8 * B_ * S_ * 2048];     // split-K partials (16 MB)
__device__ float g_Upart[B_ * NCHUNK * S_ * D_];  // 16 MB partials
__device__ float g_rspart[B_ * NCHUNK * S_];

// -------------------- small utility kernels --------------------------------
__global__ void feat_stats_kernel(const float* __restrict__ feat) {
    int row = blockIdx.x * 8 + (threadIdx.x >> 5);
    int lane = threadIdx.x & 31;
    const float4* r4 = (const float4*)(feat + (size_t)row * D_);
    float s = 0.f, ss = 0.f;
#pragma unroll
    for (int i = 0; i < 4; i++) {
        float4 v = r4[lane + 32 * i];
        s += v.x + v.y + v.z + v.w;
        ss += v.x * v.x + v.y * v.y + v.z * v.z + v.w * v.w;
    }
#pragma unroll
    for (int o = 16; o; o >>= 1) {
        s += __shfl_xor_sync(0xffffffffu, s, o);
        ss += __shfl_xor_sync(0xffffffffu, ss, o);
    }
    if (lane == 0) {
        float m = s * (1.f / D_);
        float var = ss * (1.f / D_) - m * m;
        g_stats[row * 2] = m;
        g_stats[row * 2 + 1] = rsqrtf(fmaxf(var, 0.f) + LN_EPS);
    }
}

// LayerNorm of [R, 512] rows -> Y (128 threads per row) — used only at iter 0
__global__ void ln_rows_kernel(const float* __restrict__ X, float* __restrict__ Y,
                               const float* __restrict__ w, const float* __restrict__ b) {
    __shared__ float red[48];
    int row = blockIdx.x;
    const float* x = X + (size_t)row * D_;
    int t = threadIdx.x;
    float v[4];
    float s = 0.f, ss = 0.f;
#pragma unroll
    for (int i = 0; i < 4; i++) {
        v[i] = x[t + 128 * i];
        s += v[i];
        ss += v[i] * v[i];
    }
#pragma unroll
    for (int o = 16; o; o >>= 1) {
        s += __shfl_xor_sync(0xffffffffu, s, o);
        ss += __shfl_xor_sync(0xffffffffu, ss, o);
    }
    int warp = t >> 5, lane = t & 31;
    if (lane == 0) { red[warp] = s; red[warp + 8] = ss; }
    __syncthreads();
    if (t == 0) {
        float S2 = 0.f, SS = 0.f;
        for (int wi = 0; wi < 4; wi++) { S2 += red[wi]; SS += red[wi + 8]; }
        float m = S2 * (1.f / D_);
        red[16] = m;
        red[17] = rsqrtf(fmaxf(SS * (1.f / D_) - m * m, 0.f) + LN_EPS);
    }
    __syncthreads();
    float m = red[16], r = red[17];
    float* y = Y + (size_t)row * D_;
#pragma unroll
    for (int i = 0; i < 4; i++) {
        int d = t + 128 * i;
        y[d] = (v[i] - m) * r * w[d] + b[d];
    }
}

// pack Wqkhh = [Wqk(from tmp) | w_hh^T]; bias2048 = [0 | b_hh]
__global__ void build_whh_kernel(const float* __restrict__ w_hh,
                                 const float* __restrict__ b_hh,
                                 const float* __restrict__ wqk_tmp) {
    int idx = blockIdx.x * 256 + threadIdx.x;   // < 512*2048
    int d = idx >> 11, col = idx & 2047;
    g_Wqkhh[idx] = (col < 512) ? wqk_tmp[(size_t)d * 512 + col]
                               : w_hh[(size_t)(col - 512) * 512 + d];
    if (idx < 2048) g_bias2048[idx] = (idx < 512) ? 0.f : b_hh[idx - 512];
}

// -------------------- SGEMM: 128x64x16 tiles, 256 threads, 8x4 micro --------
// Accumulators packed f32x2 along M (A-pairs free from LDS.128 of k-major As).
// Compact B smem (R11-proven). Double-buffered. Split-K slabs.
template <bool TRANS_B>
__global__ void __launch_bounds__(256, 3)
gemm128_kernel(const float* __restrict__ A, const float* __restrict__ Bm,
               float* __restrict__ C, int M, int N, int K, int ldc) {
    __shared__ __align__(16) float As[2][16][128];
    __shared__ __align__(16) float Bs[2][16][64];
    const int tid = threadIdx.x;          // 256 threads
    const int bm = blockIdx.y * 128;
    const int bn = blockIdx.x * 64;
    const int Kz = K / gridDim.z;
    const int kbase = blockIdx.z * Kz;
    C += (size_t)blockIdx.z * M * ldc;

    const int tx = tid & 15, ty = tid >> 4;   // micro: 8 rows (4 pairs) x 4 cols
    const int a_m0 = tid >> 2;                // 0..63
    const int a_k  = (tid & 3) * 4;
    const int b_k = tid >> 4, b_n = (tid & 15) * 4;
    const int bt_n = tid >> 2;                // 0..63

    float4 pa0, pa1, pb;
    u64t acc[4][4];
#pragma unroll
    for (int i = 0; i < 4; i++)
#pragma unroll
        for (int j = 0; j < 4; j++) acc[i][j] = 0ull;

    const int nsteps = Kz / 16;

    pa0 = *(const float4*)(A + (size_t)(bm + a_m0) * K + kbase + a_k);
    pa1 = *(const float4*)(A + (size_t)(bm + a_m0 + 64) * K + kbase + a_k);
    if (TRANS_B)
        pb = *(const float4*)(Bm + (size_t)(bn + bt_n) * K + kbase + a_k);
    else
        pb = *(const float4*)(Bm + (size_t)(kbase + b_k) * N + bn + b_n);

    As[0][a_k + 0][a_m0] = pa0.x; As[0][a_k + 1][a_m0] = pa0.y;
    As[0][a_k + 2][a_m0] = pa0.z; As[0][a_k + 3][a_m0] = pa0.w;
    As[0][a_k + 0][a_m0 + 64] = pa1.x; As[0][a_k + 1][a_m0 + 64] = pa1.y;
    As[0][a_k + 2][a_m0 + 64] = pa1.z; As[0][a_k + 3][a_m0 + 64] = pa1.w;
    if (TRANS_B) {
        Bs[0][a_k + 0][bt_n] = pb.x; Bs[0][a_k + 1][bt_n] = pb.y;
        Bs[0][a_k + 2][bt_n] = pb.z; Bs[0][a_k + 3][bt_n] = pb.w;
    } else {
        *(float4*)&Bs[0][b_k][b_n] = pb;
    }
    __syncthreads();

    int buf = 0;
    for (int s = 0; s < nsteps; s++) {
        if (s + 1 < nsteps) {
            int kb = kbase + (s + 1) * 16;
            pa0 = *(const float4*)(A + (size_t)(bm + a_m0) * K + kb + a_k);
            pa1 = *(const float4*)(A + (size_t)(bm + a_m0 + 64) * K + kb + a_k);
            if (TRANS_B)
                pb = *(const float4*)(Bm + (size_t)(bn + bt_n) * K + kb + a_k);
            else
                pb = *(const float4*)(Bm + (size_t)(kb + b_k) * N + bn + b_n);
        }
#pragma unroll
        for (int k = 0; k < 16; k++) {
            const ulonglong2 ap01 = *(const ulonglong2*)&As[buf][k][ty * 8];
            const ulonglong2 ap23 = *(const ulonglong2*)&As[buf][k][ty * 8 + 4];
            const float4 b4 = *(const float4*)&Bs[buf][k][tx * 4];
            u64t ap[4] = {ap01.x, ap01.y, ap23.x, ap23.y};
            u64t bd[4];
            bd[0] = f2pack(b4.x, b4.x); bd[1] = f2pack(b4.y, b4.y);
            bd[2] = f2pack(b4.z, b4.z); bd[3] = f2pack(b4.w, b4.w);
#pragma unroll
            for (int i = 0; i < 4; i++)
#pragma unroll
                for (int j = 0; j < 4; j++) f2fma(acc[i][j], ap[i], bd[j]);
        }
        if (s + 1 < nsteps) {
            int nb = buf ^ 1;
            As[nb][a_k + 0][a_m0] = pa0.x; As[nb][a_k + 1][a_m0] = pa0.y;
            As[nb][a_k + 2][a_m0] = pa0.z; As[nb][a_k + 3][a_m0] = pa0.w;
            As[nb][a_k + 0][a_m0 + 64] = pa1.x; As[nb][a_k + 1][a_m0 + 64] = pa1.y;
            As[nb][a_k + 2][a_m0 + 64] = pa1.z; As[nb][a_k + 3][a_m0 + 64] = pa1.w;
            if (TRANS_B) {
                Bs[nb][a_k + 0][bt_n] = pb.x; Bs[nb][a_k + 1][bt_n] = pb.y;
                Bs[nb][a_k + 2][bt_n] = pb.z; Bs[nb][a_k + 3][bt_n] = pb.w;
            } else {
                *(float4*)&Bs[nb][b_k][b_n] = pb;
            }
            __syncthreads();
            buf = nb;
        }
    }
#pragma unroll
    for (int i2 = 0; i2 < 4; i2++) {
        float2 c0 = f2unpack(acc[i2][0]), c1 = f2unpack(acc[i2][1]);
        float2 c2 = f2unpack(acc[i2][2]), c3 = f2unpack(acc[i2][3]);
        int r0 = bm + ty * 8 + 2 * i2;
        *(float4*)(C + (size_t)r0 * ldc + bn + tx * 4) =
            make_float4(c0.x, c1.x, c2.x, c3.x);
        *(float4*)(C + (size_t)(r0 + 1) * ldc + bn + tx * 4) =
            make_float4(c0.y, c1.y, c2.y, c3.y);
    }
}

// deterministic split-K reduce (float4): out contiguous (ldo == ncols)
template <bool RELU>
__global__ void splitk_reduce(const float* __restrict__ bias, float* __restrict__ out,
                              int n, int ncols, int nsplit, int stride) {
    int i = (blockIdx.x * 256 + threadIdx.x) * 4;
    if (i >= n) return;
    float4 v = make_float4(0.f, 0.f, 0.f, 0.f);
    for (int z = 0; z < nsplit; z++) {
        const float4 p = *(const float4*)(g_split + (size_t)z * stride + i);
        v.x += p.x; v.y += p.y; v.z += p.z; v.w += p.w;
    }
    if (bias) {
        int col = i % ncols;
        const float4 bq = *(const float4*)(bias + col);
        v.x += bq.x; v.y += bq.y; v.z += bq.z; v.w += bq.w;
    }
    if (RELU) {
        v.x = fmaxf(v.x, 0.f); v.y = fmaxf(v.y, 0.f);
        v.z = fmaxf(v.z, 0.f); v.w = fmaxf(v.w, 0.f);
    }
    *(float4*)(out + i) = v;
}

// -------------------- fused row kernels (512 threads = 1 row) ---------------
__device__ __forceinline__ void block_ln_512(float v, float* red, int t,
                                             float& m_out, float& r_out) {
    float s = v, ss = v * v;
#pragma unroll
    for (int o = 16; o; o >>= 1) {
        s += __shfl_xor_sync(0xffffffffu, s, o);
        ss += __shfl_xor_sync(0xffffffffu, ss, o);
    }
    int warp = t >> 5, lane = t & 31;
    if (lane == 0) { red[warp] = s; red[warp + 16] = ss; }
    __syncthreads();
    if (t == 0) {
        float S2 = 0.f, SS = 0.f;
#pragma unroll
        for (int wi = 0; wi < 16; wi++) { S2 += red[wi]; SS += red[wi + 16]; }
        float m = S2 * (1.f / D_);
        red[32] = m;
        red[33] = rsqrtf(fmaxf(SS * (1.f / D_) - m * m, 0.f) + LN_EPS);
    }
    __syncthreads();
    m_out = red[32];
    r_out = red[33];
}

// gi split-8 reduce + GRU combine + LN(ln_mlp) -> slots2, mlpin.
__global__ void gru_ln_kernel(const float* __restrict__ b_ih,
                              const float* __restrict__ lnw, const float* __restrict__ lnb) {
    __shared__ float red[34];
    int r = blockIdx.x, d = threadIdx.x;
    float ir = b_ih[d], iz = b_ih[D_ + d], in_ = b_ih[2 * D_ + d];
    size_t base = (size_t)r * 3 * D_ + d;
#pragma unroll
    for (int zz = 0; zz < 8; zz++) {
        const float* sl = g_split + (size_t)zz * (B_ * S_ * 3 * D_);
        ir  += sl[base];
        iz  += sl[base + D_];
        in_ += sl[base + 2 * D_];
    }
    size_t ghb = (size_t)r * 2048 + 512;
    float hr = g_qkgh[ghb + d], hz = g_qkgh[ghb + D_ + d], hn = g_qkgh[ghb + 2 * D_ + d];
    float rg = 1.f / (1.f + expf(-(ir + hr)));
    float z  = 1.f / (1.f + expf(-(iz + hz)));
    float n  = tanhf(in_ + rg * hn);
    float v  = (1.f - z) * n + z * g_sn[(size_t)r * D_ + d];
    g_slots2[(size_t)r * D_ + d] = v;
    float m, rs;
    block_ln_512(v, red, d, m, rs);
    g_mlpin[(size_t)r * D_ + d] = (v - m) * rs * lnw[d] + lnb[d];
}

// mlp2 split-16 reduce + b2 + residual(slots2) + LN(ln_slot) -> sn (+out last)
__global__ void mlp2_reduce_ln(const float* __restrict__ b2,
                               const float* __restrict__ lnw, const float* __restrict__ lnb,
                               float* __restrict__ out_slots /* null unless last */) {
    __shared__ float red[34];
    int r = blockIdx.x, d = threadIdx.x;
    size_t i = (size_t)r * D_ + d;
    float v = b2[d] + g_slots2[i];
#pragma unroll
    for (int z = 0; z < 16; z++) v += g_split[(size_t)z * (B_ * S_ * D_) + i];
    if (out_slots) out_slots[i] = v;
    float m, rs;
    block_ln_512(v, red, d, m, rs);
    g_sn[i] = (v - m) * rs * lnw[d] + lnb[d];
}

// -------------------- fused per-iteration feature pass ----------------------
// LN folded out: dots = rstd*(x.wq - mean*swq) + cq ;  U = w*(sum(beta*x)-G)+b*A
// Phase 1: warps 0-3 handle slots 0-3, warps 4-7 slots 4-7; q in registers.
__global__ void iter_pass_kernel(const float* __restrict__ feat,
                                 const float* __restrict__ lnw,
                                 const float* __restrict__ lnb,
                                 float* __restrict__ attn_out) {
    __shared__ __align__(16) float qk_s[S_ * D_];  // wq; reused as reduce buffer
    __shared__ __align__(16) float dots_s[CHUNK * S_];
    __shared__ __align__(16) float attn_s[CHUNK * S_];
    __shared__ __align__(16) u64t betasd_s[CHUNK * S_];   // duplicated (b,b)
    __shared__ __align__(16) float lnw_s[D_], lnb_s[D_];
    __shared__ float stats_s[CHUNK * 2];
    __shared__ float wsum_s[4][8], gsum_s[4][8];
    __shared__ float swq_s[8], cq_s[8], A_s[8], G_s[8];

    int chunk = blockIdx.x, b = blockIdx.y;
    int tid = threadIdx.x, warp = tid >> 5, lane = tid & 31;
    int f0 = chunk * CHUNK;

    for (int i = tid; i < D_; i += 256) { lnw_s[i] = lnw[i]; lnb_s[i] = lnb[i]; }
    for (int i = tid; i < CHUNK * 2; i += 256) stats_s[i] = g_stats[((size_t)b * F_ + f0) * 2 + i];
    __syncthreads();

    // ---- per-warp wq prep: warp w handles slot s=w ----
    {
        int s = warp;
        const float* qrow = g_qkgh + ((size_t)(b * 8 + s)) * 2048;
        float swq = 0.f, cq = 0.f;
#pragma unroll
        for (int i = 0; i < 4; i++) {
            int d4 = (lane + 32 * i) * 4;
            float4 q = *(const float4*)(qrow + d4);
            float4 w4 = *(const float4*)&lnw_s[d4];
            float4 b4 = *(const float4*)&lnb_s[d4];
            float4 wq = make_float4(q.x * w4.x, q.y * w4.y, q.z * w4.z, q.w * w4.w);
            *(float4*)&qk_s[s * D_ + d4] = wq;
            swq += wq.x + wq.y + wq.z + wq.w;
            cq  += b4.x * q.x + b4.y * q.y + b4.z * q.z + b4.w * q.w;
        }
#pragma unroll
        for (int o = 16; o; o >>= 1) {
            swq += __shfl_xor_sync(0xffffffffu, swq, o);
            cq  += __shfl_xor_sync(0xffffffffu, cq, o);
        }
        if (lane == 0) { swq_s[s] = swq; cq_s[s] = cq; }
    }
    __syncthreads();

    // ---- phase 1: register-resident q; warp group g covers slots g*4..g*4+3
    {
        const int g = warp >> 2;
        const int sp0 = g * 4;
        u64t qreg[4][8];   // [slot][pair] — lane's 16 dims x 4 slots
#pragma unroll
        for (int s = 0; s < 4; s++)
#pragma unroll
            for (int i = 0; i < 4; i++) {
                const ulonglong2 qp =
                    *(const ulonglong2*)&qk_s[(sp0 + s) * D_ + (lane + 32 * i) * 4];
                qreg[s][2 * i] = qp.x;
                qreg[s][2 * i + 1] = qp.y;
            }
        for (int fl = (warp & 3); fl < CHUNK; fl += 4) {
            const ulonglong2* r2p =
                (const ulonglong2*)(feat + ((size_t)(b * F_ + f0 + fl)) * D_);
            u64t acc4[4] = {};
#pragma unroll
            for (int i = 0; i < 4; i++) {
                const ulonglong2 xv = r2p[lane + 32 * i];
#pragma unroll
                for (int s = 0; s < 4; s++) {
                    f2fma(acc4[s], xv.x, qreg[s][2 * i]);
                    f2fma(acc4[s], xv.y, qreg[s][2 * i + 1]);
                }
            }
            float a[4];
#pragma unroll
            for (int s = 0; s < 4; s++) {
                float2 u = f2unpack(acc4[s]);
                a[s] = u.x + u.y;
            }
            // fold-reduce: lane l ends with full dot of slot sp0 + ((l>>3)&3)
            float r2v[2];
#pragma unroll
            for (int s = 0; s < 2; s++) {
                float mine  = (lane & 16) ? a[s + 2] : a[s];
                float other = (lane & 16) ? a[s] : a[s + 2];
                r2v[s] = mine + __shfl_xor_sync(0xffffffffu, other, 16);
            }
            float mine  = (lane & 8) ? r2v[1] : r2v[0];
            float other = (lane & 8) ? r2v[0] : r2v[1];
            float r1 = mine + __shfl_xor_sync(0xffffffffu, other, 8);
            r1 += __shfl_xor_sync(0xffffffffu, r1, 4);
            r1 += __shfl_xor_sync(0xffffffffu, r1, 2);
            r1 += __shfl_xor_sync(0xffffffffu, r1, 1);
            if ((lane & 7) == 0)
                dots_s[fl * 8 + sp0 + ((lane >> 3) & 3)] = r1;
        }
    }
    __syncthreads();

    // ---- softmax stage: threads 0-127, one row each ----
    if (tid < 128) {
        int fl = tid;
        const float4 d0 = *(const float4*)&dots_s[fl * 8];
        const float4 d1 = *(const float4*)&dots_s[fl * 8 + 4];
        float dv[8] = {d0.x, d0.y, d0.z, d0.w, d1.x, d1.y, d1.z, d1.w};
        float mean = stats_s[fl * 2], rstd = stats_s[fl * 2 + 1];
        float sc[8], mx;
#pragma unroll
        for (int s = 0; s < 8; s++)
            sc[s] = (rstd * (dv[s] - mean * swq_s[s]) + cq_s[s]) * SCALE_;
        mx = sc[0];
#pragma unroll
        for (int s = 1; s < 8; s++) mx = fmaxf(mx, sc[s]);
        float e[8], den = 0.f;
#pragma unroll
        for (int s = 0; s < 8; s++) { e[s] = expf(sc[s] - mx); den += e[s]; }
        float inv = 1.f / den;
        float wsum8[8], gsum8[8];
#pragma unroll
        for (int s = 0; s < 8; s++) {
            float p = e[s] * inv;
            attn_s[fl * 8 + s] = p;
            float al = p + kEPS;
            float bt = al * rstd;
            betasd_s[fl * 8 + s] = f2pack(bt, bt);
            wsum8[s] = al;
            gsum8[s] = bt * mean;
        }
        // reduce across 32 rows within each of warps 0-3
#pragma unroll
        for (int s = 0; s < 8; s++) {
#pragma unroll
            for (int o = 16; o; o >>= 1) {
                wsum8[s] += __shfl_xor_sync(0xffffffffu, wsum8[s], o);
                gsum8[s] += __shfl_xor_sync(0xffffffffu, gsum8[s], o);
            }
        }
        if (lane == 0) {
#pragma unroll
            for (int s = 0; s < 8; s++) { wsum_s[warp][s] = wsum8[s]; gsum_s[warp][s] = gsum8[s]; }
        }
    }
    __syncthreads();
    if (tid < 8) {
        float tA = 0.f, tG = 0.f;
#pragma unroll
        for (int w = 0; w < 4; w++) { tA += wsum_s[w][tid]; tG += gsum_s[w][tid]; }
        g_rspart[(b * NCHUNK + chunk) * 8 + tid] = tA;
        A_s[tid] = tA;
        G_s[tid] = tG;
    }
    if (attn_out) {
        for (int idx = tid; idx < CHUNK * S_; idx += 256) {
            int s = idx >> 7;
            int fl = idx & 127;
            attn_out[((size_t)(b * S_ + s)) * F_ + f0 + fl] = attn_s[fl * 8 + s];
        }
    }

    // ---- phase 2: sum(beta*x); x pairs free from LDG, betas dup from LDS ----
    int half = tid >> 7;              // 0: rows 0-63, 1: rows 64-127
    int d4 = (tid & 127) * 4;
    float4 w4 = *(const float4*)&lnw_s[d4];
    float4 b4 = *(const float4*)&lnb_s[d4];
    u64t accp2[2][8];                 // [col-pair][slot]
#pragma unroll
    for (int c = 0; c < 2; c++)
#pragma unroll
        for (int s = 0; s < 8; s++) accp2[c][s] = 0ull;

    int fl0 = half * 64;
    for (int fl = fl0; fl < fl0 + 64; fl++) {
        const ulonglong2 xv = *(const ulonglong2*)(feat + ((size_t)(b * F_ + f0 + fl)) * D_ + d4);
        const ulonglong2 bd01 = *(const ulonglong2*)&betasd_s[fl * 8];
        const ulonglong2 bd23 = *(const ulonglong2*)&betasd_s[fl * 8 + 2];
        const ulonglong2 bd45 = *(const ulonglong2*)&betasd_s[fl * 8 + 4];
        const ulonglong2 bd67 = *(const ulonglong2*)&betasd_s[fl * 8 + 6];
        u64t bd[8] = {bd01.x, bd01.y, bd23.x, bd23.y, bd45.x, bd45.y, bd67.x, bd67.y};
#pragma unroll
        for (int s = 0; s < 8; s++) {
            f2fma(accp2[0][s], xv.x, bd[s]);
            f2fma(accp2[1][s], xv.y, bd[s]);
        }
    }
    float4 acc8[8];
#pragma unroll
    for (int s = 0; s < 8; s++) {
        float2 u0 = f2unpack(accp2[0][s]);
        float2 u1 = f2unpack(accp2[1][s]);
        acc8[s] = make_float4(u0.x, u0.y, u1.x, u1.y);
    }
    __syncthreads();     // phase-1/softmax reads of qk_s done; reuse as buffer
    if (half == 0) {
#pragma unroll
        for (int s = 0; s < 8; s++) *(float4*)&qk_s[s * D_ + d4] = acc8[s];
    }
    __syncthreads();
    if (half == 1) {
        size_t base = ((size_t)(b * NCHUNK + chunk)) * S_ * D_;
#pragma unroll
        for (int s = 0; s < 8; s++) {
            float4 cmb = *(const float4*)&qk_s[s * D_ + d4];
            cmb.x += acc8[s].x; cmb.y += acc8[s].y;
            cmb.z += acc8[s].z; cmb.w += acc8[s].w;
            float A = A_s[s], G = G_s[s];
            float4 o;
            o.x = w4.x * (cmb.x - G) + b4.x * A;
            o.y = w4.y * (cmb.y - G) + b4.y * A;
            o.z = w4.z * (cmb.z - G) + b4.z * A;
            o.w = w4.w * (cmb.w - G) + b4.w * A;
            *(float4*)(&g_Upart[base + s * D_ + d4]) = o;
        }
    }
}

// deterministic reduction of partials + rowsum normalization
__global__ void reduce_updates_kernel() {
    int bs = blockIdx.x;           // b*8+s
    int b = bs >> 3, s = bs & 7;
    int d = threadIdx.x;           // 512 threads
    float rs = 0.f;
#pragma unroll
    for (int c = 0; c < NCHUNK; c++) rs += g_rspart[(b * NCHUNK + c) * 8 + s];
    float acc = 0.f;
    for (int c = 0; c < NCHUNK; c++)
        acc += g_Upart[(((size_t)(b * NCHUNK + c)) * S_ + s) * D_ + d];
    g_updates[(size_t)bs * D_ + d] = acc / rs;
}

// -------------------- host orchestration -----------------------------------
extern "C" void kernel_launch(void* const* d_in, const int* in_sizes, int n_in,
                              void* d_out, int out_size) {
    const float* slots_in = (const float*)d_in[0];
    const float* features = (const float*)d_in[1];
    const float* w_k      = (const float*)d_in[2];
    const float* w_v      = (const float*)d_in[3];
    const float* w_q      = (const float*)d_in[4];
    const float* ln_feat_w = (const float*)d_in[5];
    const float* ln_feat_b = (const float*)d_in[6];
    const float* ln_slot_w = (const float*)d_in[7];
    const float* ln_slot_b = (const float*)d_in[8];
    const float* gru_w_ih = (const float*)d_in[9];
    const float* gru_w_hh = (const float*)d_in[10];
    const float* gru_b_ih = (const float*)d_in[11];
    const float* gru_b_hh = (const float*)d_in[12];
    const float* ln_mlp_w = (const float*)d_in[13];
    const float* ln_mlp_b = (const float*)d_in[14];
    const float* mlp_w1   = (const float*)d_in[15];
    const float* mlp_b1   = (const float*)d_in[16];
    const float* mlp_w2   = (const float*)d_in[17];
    const float* mlp_b2   = (const float*)d_in[18];

    float* out = (float*)d_out;
    float* out_slots = out;                      // [32,8,512]
    float* out_attn  = out + B_ * S_ * D_;       // [32,8,4096]

    float *p_Wqkhh, *p_bias2048, *p_Wvih, *p_sn, *p_qkgh, *p_gi,
          *p_updates, *p_mlpin, *p_hbuf, *p_split;
    cudaGetSymbolAddress((void**)&p_Wqkhh, g_Wqkhh);
    cudaGetSymbolAddress((void**)&p_bias2048, g_bias2048);
    cudaGetSymbolAddress((void**)&p_Wvih, g_Wvih);
    cudaGetSymbolAddress((void**)&p_sn, g_sn);
    cudaGetSymbolAddress((void**)&p_qkgh, g_qkgh);
    cudaGetSymbolAddress((void**)&p_gi, g_gi);
    cudaGetSymbolAddress((void**)&p_updates, g_updates);
    cudaGetSymbolAddress((void**)&p_mlpin, g_mlpin);
    cudaGetSymbolAddress((void**)&p_hbuf, g_hbuf);
    cudaGetSymbolAddress((void**)&p_split, g_split);

    const int NS = B_ * S_;          // 256 slot rows

    // -------- precomputes --------
    feat_stats_kernel<<<(B_ * F_) / 8, 256>>>(features);
    // Wqk tmp = w_q @ w_k^T  (NT, split-8 Kz=64) -> g_gi tmp
    gemm128_kernel<true><<<dim3(8, 4, 8), 256>>>(w_q, w_k, p_split, D_, D_, D_, D_);
    splitk_reduce<false><<<(512 * 512 / 4 + 255) / 256, 256>>>(nullptr, p_gi,
        512 * 512, 512, 8, 512 * 512);
    // W_vih = w_v @ w_ih^T  (NT, split-4 Kz=128)
    gemm128_kernel<true><<<dim3(24, 4, 4), 256>>>(w_v, gru_w_ih, p_split, D_, 3 * D_, D_, 3 * D_);
    splitk_reduce<false><<<(512 * 1536 / 4 + 255) / 256, 256>>>(nullptr, p_Wvih,
        512 * 1536, 1536, 4, 512 * 1536);
    // pack Wqkhh + bias
    build_whh_kernel<<<(512 * 2048) / 256, 256>>>(gru_w_hh, gru_b_hh, p_gi);

    for (int it = 0; it < NITERS_; it++) {
        bool last = (it == NITERS_ - 1);

        if (it == 0)
            ln_rows_kernel<<<NS, 128>>>(slots_in, p_sn, ln_slot_w, ln_slot_b);

        // [qk | gh] = s_n @ Wqkhh + [0 | b_hh]   (NN, N=2048, split-8 Kz=64)
        gemm128_kernel<false><<<dim3(32, 2, 8), 256>>>(p_sn, p_Wqkhh, p_split,
                                                       NS, 2048, D_, 2048);
        splitk_reduce<false><<<(NS * 2048 / 4 + 255) / 256, 256>>>(p_bias2048, p_qkgh,
            NS * 2048, 2048, 8, NS * 2048);

        // fused attention pass over features
        iter_pass_kernel<<<dim3(NCHUNK, B_), 256>>>(features, ln_feat_w, ln_feat_b,
                                                    last ? out_attn : nullptr);
        reduce_updates_kernel<<<NS, D_>>>();

        // gi partials = updates @ W_vih   (NN, N=1536, split-8 Kz=64)
        gemm128_kernel<false><<<dim3(24, 2, 8), 256>>>(p_updates, p_Wvih, p_split,
                                                       NS, 3 * D_, D_, 3 * D_);
        // fused: gi reduce + b_ih + GRU combine + LN(mlp)
        gru_ln_kernel<<<NS, D_>>>(gru_b_ih, ln_mlp_w, ln_mlp_b);

        // mlp1 = relu(mlpin @ w1 + b1)   (NN, N=2048, split-8 Kz=64)
        gemm128_kernel<false><<<dim3(32, 2, 8), 256>>>(p_mlpin, mlp_w1, p_split,
                                                       NS, H_, D_, H_);
        splitk_reduce<true><<<(NS * 2048 / 4 + 255) / 256, 256>>>(mlp_b1, p_hbuf,
            NS * 2048, 2048, 8, NS * 2048);

        // mlp2 partials (NN, N=512, K=2048, split-16 Kz=128)
        gemm128_kernel<false><<<dim3(8, 2, 16), 256>>>(p_hbuf, mlp_w2, p_split,
                                                       NS, D_, H_, D_);
        // reduce + bias + residual + LN(slot) -> sn (and out_slots if last)
        mlp2_reduce_ln<<<NS, D_>>>(mlp_b2, ln_slot_w, ln_slot_b,
                                   last ? out_slots : nullptr);
    }
}